// round 9
// baseline (speedup 1.0000x reference)
#include <cuda_runtime.h>
#include <cstdint>

// Problem constants
#define BB 4
#define SS 2048
#define HH 2048
#define NH 16
#define HD 128
#define MM (BB*SS)            // 8192 rows

// Scratch (allocation-free: __device__ globals)
__device__ float g_q[BB*NH*SS*HD];   // [b,h,s,d]  (tf32-rounded)
__device__ float g_k[BB*NH*SS*HD];
__device__ float g_v[BB*NH*SS*HD];
__device__ float g_o[MM*HH];         // [b,s,h*d]  (tf32-rounded)
__device__ float g_x[MM*HH];         // tf32-rounded x
__device__ float g_w[4][HH*HH];      // tf32-rounded weights (q,k,v,o)

__device__ __forceinline__ uint32_t f2tf(float f) {
    uint32_t u; asm("cvt.rna.tf32.f32 %0, %1;" : "=r"(u) : "f"(f)); return u;
}

__device__ __forceinline__ void mma_m16n8k8(float c[4], const uint32_t a[4], const uint32_t b[2]) {
    asm volatile(
        "mma.sync.aligned.m16n8k8.row.col.f32.tf32.tf32.f32 "
        "{%0,%1,%2,%3},{%4,%5,%6,%7},{%8,%9},{%0,%1,%2,%3};"
        : "+f"(c[0]), "+f"(c[1]), "+f"(c[2]), "+f"(c[3])
        : "r"(a[0]), "r"(a[1]), "r"(a[2]), "r"(a[3]), "r"(b[0]), "r"(b[1]));
}

__device__ __forceinline__ void cpa16(uint32_t s, const float* g) {
    asm volatile("cp.async.cg.shared.global [%0], [%1], 16;\n" :: "r"(s), "l"(g));
}
__device__ __forceinline__ void cpa_commit() {
    asm volatile("cp.async.commit_group;\n" ::: "memory");
}
template<int N> __device__ __forceinline__ void cpa_wait() {
    asm volatile("cp.async.wait_group %0;\n" :: "n"(N) : "memory");
}

// ============================================================================
// Elementwise tf32 rounding pass
// ============================================================================
__global__ void round_tf32_kernel(const float* __restrict__ in, float* __restrict__ out, int n4) {
    int i = blockIdx.x * blockDim.x + threadIdx.x;
    if (i < n4) {
        float4 f = reinterpret_cast<const float4*>(in)[i];
        uint4 u;
        u.x = f2tf(f.x); u.y = f2tf(f.y); u.z = f2tf(f.z); u.w = f2tf(f.w);
        reinterpret_cast<uint4*>(out)[i] = u;
    }
}

// ============================================================================
// GEMM: C[M,N] = A[M,K] * Bw[N,K]^T   (tf32 mma, CTA tile 256x128, BK=32,
// warp tile 64x64 -> 1.0 LDS per HMMA, 3-stage cp.async, 256 thr)
// qkv_mode=1: scatter + tf32-round C -> out[b,h,s,d] layout
// ============================================================================
#define GBK 32
#define GSTG 3
#define GAS 36    // smem row stride (floats): 36 mod 32 = 4 -> conflict-free frags
#define A_STAGE (256 * GAS)             // floats per A stage
#define B_STAGE (128 * GAS)             // floats per B stage
#define GEMM_SMEM (GSTG * (A_STAGE + B_STAGE) * 4)   // 165888 bytes

__global__ void __launch_bounds__(256, 1) gemm_tf32_kernel(
    const float* __restrict__ A, const float* __restrict__ Bw,
    float* __restrict__ C, int qkv_mode)
{
    const int K = HH, N = HH;
    extern __shared__ float sm[];
    float* As = sm;                         // [GSTG][256][GAS]
    float* Bs = sm + GSTG * A_STAGE;        // [GSTG][128][GAS]

    const int tid  = threadIdx.x;
    const int lane = tid & 31;
    const int warp = tid >> 5;
    const int g = lane >> 2, t = lane & 3;
    const int wm = warp & 3, wn = warp >> 2;     // 4 x 2 warp grid, warp tile 64x64
    const int rowBase = blockIdx.y * 256;
    const int colBase = blockIdx.x * 128;

    const uint32_t sA = (uint32_t)__cvta_generic_to_shared(As);
    const uint32_t sB = (uint32_t)__cvta_generic_to_shared(Bs);

    const float* gA = A  + (size_t)rowBase * K;
    const float* gB = Bw + (size_t)colBase * K;

    // A: 256 rows x 8 granules = 2048; 8 per thread.  B: 128 x 8 = 1024; 4 per thread.
    auto load_stage = [&](int s, int kt) {
        uint32_t bA = sA + (uint32_t)(s * A_STAGE) * 4u;
        uint32_t bB = sB + (uint32_t)(s * B_STAGE) * 4u;
        const float* pA = gA + kt * GBK;
        const float* pB = gB + kt * GBK;
        #pragma unroll
        for (int i = 0; i < 8; i++) {
            int gi = i * 256 + tid;
            int r = gi >> 3, c = (gi & 7) * 4;
            cpa16(bA + (uint32_t)(r * GAS + c) * 4u, pA + (size_t)r * K + c);
        }
        #pragma unroll
        for (int i = 0; i < 4; i++) {
            int gi = i * 256 + tid;
            int r = gi >> 3, c = (gi & 7) * 4;
            cpa16(bB + (uint32_t)(r * GAS + c) * 4u, pB + (size_t)r * K + c);
        }
        cpa_commit();
    };

    float acc[4][8][4];
    #pragma unroll
    for (int mi = 0; mi < 4; mi++)
        #pragma unroll
        for (int ni = 0; ni < 8; ni++)
            #pragma unroll
            for (int j = 0; j < 4; j++) acc[mi][ni][j] = 0.f;

    load_stage(0, 0);
    load_stage(1, 1);
    cpa_wait<1>();
    __syncthreads();

    const int nk = K / GBK;   // 64
    #pragma unroll 1
    for (int kt = 0; kt < nk; kt++) {
        const int cur = kt % GSTG;
        if (kt + 2 < nk) load_stage((kt + 2) % GSTG, kt + 2);
        else             cpa_commit();

        const float* Ac = As + cur * A_STAGE;
        const float* Bc = Bs + cur * B_STAGE;

        #pragma unroll
        for (int kk = 0; kk < 4; kk++) {
            uint32_t a[4][4];
            #pragma unroll
            for (int mi = 0; mi < 4; mi++) {
                int r = wm * 64 + mi * 16 + g;
                a[mi][0] = __float_as_uint(Ac[r * GAS + kk * 8 + t]);
                a[mi][1] = __float_as_uint(Ac[(r + 8) * GAS + kk * 8 + t]);
                a[mi][2] = __float_as_uint(Ac[r * GAS + kk * 8 + t + 4]);
                a[mi][3] = __float_as_uint(Ac[(r + 8) * GAS + kk * 8 + t + 4]);
            }
            #pragma unroll
            for (int ni = 0; ni < 8; ni++) {
                uint32_t bf[2];
                int bn = wn * 64 + ni * 8 + g;
                bf[0] = __float_as_uint(Bc[bn * GAS + kk * 8 + t]);
                bf[1] = __float_as_uint(Bc[bn * GAS + kk * 8 + t + 4]);
                #pragma unroll
                for (int mi = 0; mi < 4; mi++)
                    mma_m16n8k8(acc[mi][ni], a[mi], bf);
            }
        }
        cpa_wait<1>();
        __syncthreads();
    }

    // epilogue
    #pragma unroll
    for (int mi = 0; mi < 4; mi++) {
        int r0 = rowBase + wm * 64 + mi * 16 + g;
        #pragma unroll
        for (int ni = 0; ni < 8; ni++) {
            int cc = colBase + wn * 64 + ni * 8 + 2 * t;
            if (!qkv_mode) {
                float* dst = C + (size_t)r0 * N + cc;
                *reinterpret_cast<float2*>(dst)           = make_float2(acc[mi][ni][0], acc[mi][ni][1]);
                *reinterpret_cast<float2*>(dst + 8ull*N)  = make_float2(acc[mi][ni][2], acc[mi][ni][3]);
            } else {
                int bb2 = r0 >> 11;
                int ss2 = r0 & 2047;
                int hh2 = cc >> 7;
                int dd  = cc & 127;
                float* dst = C + (((size_t)(bb2 * NH + hh2)) << 18) + (size_t)ss2 * HD + dd;
                float2 v0 = make_float2(__uint_as_float(f2tf(acc[mi][ni][0])),
                                        __uint_as_float(f2tf(acc[mi][ni][1])));
                float2 v1 = make_float2(__uint_as_float(f2tf(acc[mi][ni][2])),
                                        __uint_as_float(f2tf(acc[mi][ni][3])));
                *reinterpret_cast<float2*>(dst)          = v0;
                *reinterpret_cast<float2*>(dst + 8 * HD) = v1;
            }
        }
    }
}

// ============================================================================
// Flash attention (causal), tf32 mma. Q tile 128, K/V tile 64, 256 threads.
// (unchanged from round 6)
// ============================================================================
#define QS_STRIDE 132
#define KS_STRIDE 132
#define VS_STRIDE 136
#define PS_STRIDE 68

#define ATTN_SMEM ((128*QS_STRIDE + 2*64*KS_STRIDE + 64*VS_STRIDE + 128*PS_STRIDE) * 4)

__global__ void __launch_bounds__(256) attn_kernel()
{
    extern __shared__ float smf[];
    float* Qs = smf;
    float* Ks = Qs + 128 * QS_STRIDE;
    float* Vs = Ks + 2 * 64 * KS_STRIDE;
    float* Ps = Vs + 64 * VS_STRIDE;

    const int tid  = threadIdx.x;
    const int lane = tid & 31;
    const int warp = tid >> 5;
    const int g = lane >> 2, t = lane & 3;

    const int qt = blockIdx.x;
    const int h  = blockIdx.y;
    const int b  = blockIdx.z;

    const size_t base = ((size_t)(b * NH + h)) << 18;
    const float* Qg = g_q + base + (size_t)qt * 128 * HD;
    const float* Kg = g_k + base;
    const float* Vg = g_v + base;

    const uint32_t sQ = (uint32_t)__cvta_generic_to_shared(Qs);
    const uint32_t sK = (uint32_t)__cvta_generic_to_shared(Ks);
    const uint32_t sV = (uint32_t)__cvta_generic_to_shared(Vs);

    const int lr = tid >> 3;
    const int lc = (tid & 7) * 4;

    #pragma unroll
    for (int i = 0; i < 4; i++) {
        int r = lr + i * 32;
        #pragma unroll
        for (int j = 0; j < 4; j++)
            cpa16(sQ + (uint32_t)(r * QS_STRIDE + j * 32 + lc) * 4u,
                  Qg + (size_t)r * HD + j * 32 + lc);
    }
    cpa_commit();

    #pragma unroll
    for (int i = 0; i < 2; i++) {
        int r = lr + i * 32;
        #pragma unroll
        for (int j = 0; j < 4; j++)
            cpa16(sK + (uint32_t)(r * KS_STRIDE + j * 32 + lc) * 4u,
                  Kg + (size_t)r * HD + j * 32 + lc);
    }
    cpa_commit();

    float o[16][4];
    #pragma unroll
    for (int ni = 0; ni < 16; ni++)
        #pragma unroll
        for (int j = 0; j < 4; j++) o[ni][j] = 0.f;

    const float NEGINF = -1e30f;
    float mrow0 = NEGINF, mrow1 = NEGINF;
    float lrow0 = 0.f,    lrow1 = 0.f;
    const float sl = 0.088388347648318447f * 1.4426950408889634f;

    const int qrow = warp * 16 + g;
    const int nkt = 2 * qt + 2;

    #pragma unroll 1
    for (int kt = 0; kt < nkt; kt++) {
        const int cur = kt & 1, nxt = cur ^ 1;

        {
            const float* Vg4 = Vg + (size_t)kt * 64 * HD;
            #pragma unroll
            for (int i = 0; i < 2; i++) {
                int r = lr + i * 32;
                #pragma unroll
                for (int j = 0; j < 4; j++)
                    cpa16(sV + (uint32_t)(r * VS_STRIDE + j * 32 + lc) * 4u,
                          Vg4 + (size_t)r * HD + j * 32 + lc);
            }
            cpa_commit();
        }
        if (kt + 1 < nkt) {
            const float* Kg4 = Kg + (size_t)(kt + 1) * 64 * HD;
            uint32_t bK = sK + (uint32_t)(nxt * 64 * KS_STRIDE) * 4u;
            #pragma unroll
            for (int i = 0; i < 2; i++) {
                int r = lr + i * 32;
                #pragma unroll
                for (int j = 0; j < 4; j++)
                    cpa16(bK + (uint32_t)(r * KS_STRIDE + j * 32 + lc) * 4u,
                          Kg4 + (size_t)r * HD + j * 32 + lc);
            }
        }
        cpa_commit();

        cpa_wait<2>();
        __syncthreads();

        const float* Kc = Ks + cur * 64 * KS_STRIDE;

        float s[8][4];
        #pragma unroll
        for (int ni = 0; ni < 8; ni++)
            #pragma unroll
            for (int j = 0; j < 4; j++) s[ni][j] = 0.f;

        #pragma unroll
        for (int kk = 0; kk < 16; kk++) {
            uint32_t a[4];
            a[0] = __float_as_uint(Qs[qrow       * QS_STRIDE + kk * 8 + t]);
            a[1] = __float_as_uint(Qs[(qrow + 8) * QS_STRIDE + kk * 8 + t]);
            a[2] = __float_as_uint(Qs[qrow       * QS_STRIDE + kk * 8 + t + 4]);
            a[3] = __float_as_uint(Qs[(qrow + 8) * QS_STRIDE + kk * 8 + t + 4]);
            #pragma unroll
            for (int ni = 0; ni < 8; ni++) {
                uint32_t bf[2];
                int kr = ni * 8 + g;
                bf[0] = __float_as_uint(Kc[kr * KS_STRIDE + kk * 8 + t]);
                bf[1] = __float_as_uint(Kc[kr * KS_STRIDE + kk * 8 + t + 4]);
                mma_m16n8k8(s[ni], a, bf);
            }
        }

        #pragma unroll
        for (int ni = 0; ni < 8; ni++)
            #pragma unroll
            for (int j = 0; j < 4; j++) s[ni][j] *= sl;

        if (kt >= 2 * qt) {
            int q0 = qt * 128 + qrow;
            #pragma unroll
            for (int ni = 0; ni < 8; ni++) {
                int kg = kt * 64 + ni * 8 + 2 * t;
                if (kg     > q0)     s[ni][0] = NEGINF;
                if (kg + 1 > q0)     s[ni][1] = NEGINF;
                if (kg     > q0 + 8) s[ni][2] = NEGINF;
                if (kg + 1 > q0 + 8) s[ni][3] = NEGINF;
            }
        }

        float mx0 = NEGINF, mx1 = NEGINF;
        #pragma unroll
        for (int ni = 0; ni < 8; ni++) {
            mx0 = fmaxf(mx0, fmaxf(s[ni][0], s[ni][1]));
            mx1 = fmaxf(mx1, fmaxf(s[ni][2], s[ni][3]));
        }
        mx0 = fmaxf(mx0, __shfl_xor_sync(0xffffffffu, mx0, 1));
        mx0 = fmaxf(mx0, __shfl_xor_sync(0xffffffffu, mx0, 2));
        mx1 = fmaxf(mx1, __shfl_xor_sync(0xffffffffu, mx1, 1));
        mx1 = fmaxf(mx1, __shfl_xor_sync(0xffffffffu, mx1, 2));

        float mn0 = fmaxf(mrow0, mx0), mn1 = fmaxf(mrow1, mx1);
        float al0 = exp2f(mrow0 - mn0), al1 = exp2f(mrow1 - mn1);
        mrow0 = mn0; mrow1 = mn1;

        float rs0 = 0.f, rs1 = 0.f;
        #pragma unroll
        for (int ni = 0; ni < 8; ni++) {
            s[ni][0] = exp2f(s[ni][0] - mn0); rs0 += s[ni][0];
            s[ni][1] = exp2f(s[ni][1] - mn0); rs0 += s[ni][1];
            s[ni][2] = exp2f(s[ni][2] - mn1); rs1 += s[ni][2];
            s[ni][3] = exp2f(s[ni][3] - mn1); rs1 += s[ni][3];
        }
        rs0 += __shfl_xor_sync(0xffffffffu, rs0, 1);
        rs0 += __shfl_xor_sync(0xffffffffu, rs0, 2);
        rs1 += __shfl_xor_sync(0xffffffffu, rs1, 1);
        rs1 += __shfl_xor_sync(0xffffffffu, rs1, 2);
        lrow0 = lrow0 * al0 + rs0;
        lrow1 = lrow1 * al1 + rs1;

        #pragma unroll
        for (int ni = 0; ni < 16; ni++) {
            o[ni][0] *= al0; o[ni][1] *= al0;
            o[ni][2] *= al1; o[ni][3] *= al1;
        }

        #pragma unroll
        for (int ni = 0; ni < 8; ni++) {
            int col = ni * 8 + 2 * t;
            Ps[qrow       * PS_STRIDE + col    ] = __uint_as_float(f2tf(s[ni][0]));
            Ps[qrow       * PS_STRIDE + col + 1] = __uint_as_float(f2tf(s[ni][1]));
            Ps[(qrow + 8) * PS_STRIDE + col    ] = __uint_as_float(f2tf(s[ni][2]));
            Ps[(qrow + 8) * PS_STRIDE + col + 1] = __uint_as_float(f2tf(s[ni][3]));
        }
        __syncwarp();

        cpa_wait<1>();
        __syncthreads();

        #pragma unroll
        for (int kc = 0; kc < 8; kc++) {
            uint32_t a[4];
            a[0] = __float_as_uint(Ps[qrow       * PS_STRIDE + kc * 8 + t]);
            a[1] = __float_as_uint(Ps[(qrow + 8) * PS_STRIDE + kc * 8 + t]);
            a[2] = __float_as_uint(Ps[qrow       * PS_STRIDE + kc * 8 + t + 4]);
            a[3] = __float_as_uint(Ps[(qrow + 8) * PS_STRIDE + kc * 8 + t + 4]);
            #pragma unroll
            for (int ni = 0; ni < 16; ni++) {
                uint32_t bf[2];
                bf[0] = __float_as_uint(Vs[(kc * 8 + t    ) * VS_STRIDE + ni * 8 + g]);
                bf[1] = __float_as_uint(Vs[(kc * 8 + t + 4) * VS_STRIDE + ni * 8 + g]);
                mma_m16n8k8(o[ni], a, bf);
            }
        }
        __syncthreads();
    }

    float i0 = 1.f / lrow0, i1 = 1.f / lrow1;
    int qg = qt * 128 + qrow;
    float* Og = g_o + ((size_t)(b * SS + qg)) * HH + h * HD;
    #pragma unroll
    for (int ni = 0; ni < 16; ni++) {
        int d = ni * 8 + 2 * t;
        float2 v0 = make_float2(__uint_as_float(f2tf(o[ni][0] * i0)),
                                __uint_as_float(f2tf(o[ni][1] * i0)));
        float2 v1 = make_float2(__uint_as_float(f2tf(o[ni][2] * i1)),
                                __uint_as_float(f2tf(o[ni][3] * i1)));
        *reinterpret_cast<float2*>(&Og[d])             = v0;
        *reinterpret_cast<float2*>(&Og[8ull * HH + d]) = v1;
    }
}

// ============================================================================
extern "C" void kernel_launch(void* const* d_in, const int* in_sizes, int n_in,
                              void* d_out, int out_size) {
    const float* x  = (const float*)d_in[0];
    const float* wq = (const float*)d_in[1];
    const float* wk = (const float*)d_in[2];
    const float* wv = (const float*)d_in[3];
    const float* wo = (const float*)d_in[4];
    float* out = (float*)d_out;

    float *q, *k, *v, *o, *xr, *wr;
    cudaGetSymbolAddress((void**)&q,  g_q);
    cudaGetSymbolAddress((void**)&k,  g_k);
    cudaGetSymbolAddress((void**)&v,  g_v);
    cudaGetSymbolAddress((void**)&o,  g_o);
    cudaGetSymbolAddress((void**)&xr, g_x);
    cudaGetSymbolAddress((void**)&wr, g_w);

    cudaFuncSetAttribute(gemm_tf32_kernel, cudaFuncAttributeMaxDynamicSharedMemorySize, GEMM_SMEM);
    cudaFuncSetAttribute(attn_kernel,      cudaFuncAttributeMaxDynamicSharedMemorySize, ATTN_SMEM);

    // pre-round inputs to tf32
    const int XN4 = MM * HH / 4;
    const int WN4 = HH * HH / 4;
    round_tf32_kernel<<<(XN4 + 255) / 256, 256>>>(x,  xr, XN4);
    round_tf32_kernel<<<(WN4 + 255) / 256, 256>>>(wq, wr + 0ull * HH * HH, WN4);
    round_tf32_kernel<<<(WN4 + 255) / 256, 256>>>(wk, wr + 1ull * HH * HH, WN4);
    round_tf32_kernel<<<(WN4 + 255) / 256, 256>>>(wv, wr + 2ull * HH * HH, WN4);
    round_tf32_kernel<<<(WN4 + 255) / 256, 256>>>(wo, wr + 3ull * HH * HH, WN4);

    dim3 gblk(256);
    dim3 ggrd(HH / 128, MM / 256);   // (16, 32)

    gemm_tf32_kernel<<<ggrd, gblk, GEMM_SMEM>>>(xr, wr + 0ull * HH * HH, q, 1);
    gemm_tf32_kernel<<<ggrd, gblk, GEMM_SMEM>>>(xr, wr + 1ull * HH * HH, k, 1);
    gemm_tf32_kernel<<<ggrd, gblk, GEMM_SMEM>>>(xr, wr + 2ull * HH * HH, v, 1);

    attn_kernel<<<dim3(SS / 128, NH, BB), 256, ATTN_SMEM>>>();

    gemm_tf32_kernel<<<ggrd, gblk, GEMM_SMEM>>>(o, wr + 3ull * HH * HH, out, 0);
}

// round 10
// speedup vs baseline: 1.1253x; 1.1253x over previous
#include <cuda_runtime.h>
#include <cstdint>

// Problem constants
#define BB 4
#define SS 2048
#define HH 2048
#define NH 16
#define HD 128
#define MM (BB*SS)            // 8192 rows

// Scratch (allocation-free: __device__ globals)
__device__ float g_q[BB*NH*SS*HD];   // [b,h,s,d]  (tf32-rounded)
__device__ float g_k[BB*NH*SS*HD];
__device__ float g_v[BB*NH*SS*HD];
__device__ float g_o[MM*HH];         // [b,s,h*d]  (tf32-rounded)
__device__ float g_x[MM*HH];         // tf32-rounded x
__device__ float g_w[4][HH*HH];      // tf32-rounded weights (q,k,v,o)

__device__ __forceinline__ uint32_t f2tf(float f) {
    uint32_t u; asm("cvt.rna.tf32.f32 %0, %1;" : "=r"(u) : "f"(f)); return u;
}

__device__ __forceinline__ void mma_m16n8k8(float c[4], const uint32_t a[4], const uint32_t b[2]) {
    asm volatile(
        "mma.sync.aligned.m16n8k8.row.col.f32.tf32.tf32.f32 "
        "{%0,%1,%2,%3},{%4,%5,%6,%7},{%8,%9},{%0,%1,%2,%3};"
        : "+f"(c[0]), "+f"(c[1]), "+f"(c[2]), "+f"(c[3])
        : "r"(a[0]), "r"(a[1]), "r"(a[2]), "r"(a[3]), "r"(b[0]), "r"(b[1]));
}

__device__ __forceinline__ void cpa16(uint32_t s, const float* g) {
    asm volatile("cp.async.cg.shared.global [%0], [%1], 16;\n" :: "r"(s), "l"(g));
}
__device__ __forceinline__ void cpa_commit() {
    asm volatile("cp.async.commit_group;\n" ::: "memory");
}
template<int N> __device__ __forceinline__ void cpa_wait() {
    asm volatile("cp.async.wait_group %0;\n" :: "n"(N) : "memory");
}

// ============================================================================
// Elementwise tf32 rounding pass
// ============================================================================
__global__ void round_tf32_kernel(const float* __restrict__ in, float* __restrict__ out, int n4) {
    int i = blockIdx.x * blockDim.x + threadIdx.x;
    if (i < n4) {
        float4 f = reinterpret_cast<const float4*>(in)[i];
        uint4 u;
        u.x = f2tf(f.x); u.y = f2tf(f.y); u.z = f2tf(f.z); u.w = f2tf(f.w);
        reinterpret_cast<uint4*>(out)[i] = u;
    }
}

// ============================================================================
// GEMM: C[M,N] = A[M,K] * W[N,K]^T   (tf32 mma, 128x128x32 tiles, 3-stage
// cp.async pipeline, 256 thr, 2 CTAs/SM for barrier-latency hiding).
// qkv_mode=1: W = Wbase + z*HH*HH, C = {Cq,Ck,Cv}[z], scatter+round to
//             [b,h,s,d]. qkv_mode=0: plain C[M,N] = A W^T (z must be 0).
// ============================================================================
#define GBK 32
#define GSTG 3
#define GAS 36    // smem row stride (floats): 36 mod 32 = 4 -> conflict-free frags
#define GEMM_SMEM (GSTG * 2 * 128 * GAS * 4)   // 110592 bytes -> 2 CTAs/SM

__global__ void __launch_bounds__(256, 2) gemm_tf32_kernel(
    const float* __restrict__ A, const float* __restrict__ Wbase,
    float* __restrict__ Cq, float* __restrict__ Ck, float* __restrict__ Cv,
    int qkv_mode)
{
    const int K = HH, N = HH;
    extern __shared__ float sm[];
    float* As = sm;                         // [GSTG][128][GAS]
    float* Bs = sm + GSTG * 128 * GAS;

    const int tid  = threadIdx.x;
    const int lane = tid & 31;
    const int warp = tid >> 5;
    const int g = lane >> 2, t = lane & 3;
    const int wm = warp & 3, wn = warp >> 2;     // 4 x 2 warp grid, warp tile 32x64
    const int rowBase = blockIdx.y * 128;
    const int colBase = blockIdx.x * 128;
    const int z = blockIdx.z;

    const float* Bw = Wbase + (size_t)z * HH * HH;
    float* C = (z == 0) ? Cq : (z == 1) ? Ck : Cv;

    const int lr = tid >> 3;        // 0..31
    const int lc = (tid & 7) * 4;   // 0,4,..,28

    const uint32_t sA = (uint32_t)__cvta_generic_to_shared(As);
    const uint32_t sB = (uint32_t)__cvta_generic_to_shared(Bs);

    const float* gA = A  + (size_t)rowBase * K;
    const float* gB = Bw + (size_t)colBase * K;

    auto load_stage = [&](int s, int kt) {
        uint32_t bA = sA + (uint32_t)(s * 128 * GAS) * 4u;
        uint32_t bB = sB + (uint32_t)(s * 128 * GAS) * 4u;
        const float* pA = gA + kt * GBK;
        const float* pB = gB + kt * GBK;
        #pragma unroll
        for (int i = 0; i < 4; i++) {
            int r = lr + i * 32;
            cpa16(bA + (uint32_t)(r * GAS + lc) * 4u, pA + (size_t)r * K + lc);
            cpa16(bB + (uint32_t)(r * GAS + lc) * 4u, pB + (size_t)r * K + lc);
        }
        cpa_commit();
    };

    float acc[2][8][4];
    #pragma unroll
    for (int mi = 0; mi < 2; mi++)
        #pragma unroll
        for (int ni = 0; ni < 8; ni++)
            #pragma unroll
            for (int j = 0; j < 4; j++) acc[mi][ni][j] = 0.f;

    load_stage(0, 0);
    load_stage(1, 1);
    cpa_wait<1>();
    __syncthreads();

    const int nk = K / GBK;   // 64
    #pragma unroll 1
    for (int kt = 0; kt < nk; kt++) {
        const int cur = kt % GSTG;
        if (kt + 2 < nk) load_stage((kt + 2) % GSTG, kt + 2);
        else             cpa_commit();

        const float* Ac = As + cur * 128 * GAS;
        const float* Bc = Bs + cur * 128 * GAS;

        #pragma unroll
        for (int kk = 0; kk < 4; kk++) {
            uint32_t a[2][4];
            #pragma unroll
            for (int mi = 0; mi < 2; mi++) {
                int r = wm * 32 + mi * 16 + g;
                a[mi][0] = __float_as_uint(Ac[r * GAS + kk * 8 + t]);
                a[mi][1] = __float_as_uint(Ac[(r + 8) * GAS + kk * 8 + t]);
                a[mi][2] = __float_as_uint(Ac[r * GAS + kk * 8 + t + 4]);
                a[mi][3] = __float_as_uint(Ac[(r + 8) * GAS + kk * 8 + t + 4]);
            }
            #pragma unroll
            for (int ni = 0; ni < 8; ni++) {
                uint32_t bf[2];
                int bn = wn * 64 + ni * 8 + g;
                bf[0] = __float_as_uint(Bc[bn * GAS + kk * 8 + t]);
                bf[1] = __float_as_uint(Bc[bn * GAS + kk * 8 + t + 4]);
                mma_m16n8k8(acc[0][ni], a[0], bf);
                mma_m16n8k8(acc[1][ni], a[1], bf);
            }
        }
        cpa_wait<1>();
        __syncthreads();
    }

    // epilogue
    #pragma unroll
    for (int mi = 0; mi < 2; mi++) {
        int r0 = rowBase + wm * 32 + mi * 16 + g;
        #pragma unroll
        for (int ni = 0; ni < 8; ni++) {
            int cc = colBase + wn * 64 + ni * 8 + 2 * t;
            if (!qkv_mode) {
                float* dst = C + (size_t)r0 * N + cc;
                *reinterpret_cast<float2*>(dst)           = make_float2(acc[mi][ni][0], acc[mi][ni][1]);
                *reinterpret_cast<float2*>(dst + 8ull*N)  = make_float2(acc[mi][ni][2], acc[mi][ni][3]);
            } else {
                int bb2 = r0 >> 11;
                int ss2 = r0 & 2047;
                int hh2 = cc >> 7;
                int dd  = cc & 127;
                float* dst = C + (((size_t)(bb2 * NH + hh2)) << 18) + (size_t)ss2 * HD + dd;
                float2 v0 = make_float2(__uint_as_float(f2tf(acc[mi][ni][0])),
                                        __uint_as_float(f2tf(acc[mi][ni][1])));
                float2 v1 = make_float2(__uint_as_float(f2tf(acc[mi][ni][2])),
                                        __uint_as_float(f2tf(acc[mi][ni][3])));
                *reinterpret_cast<float2*>(dst)          = v0;
                *reinterpret_cast<float2*>(dst + 8 * HD) = v1;
            }
        }
    }
}

// ============================================================================
// Flash attention (causal), tf32 mma. Q tile 128, K/V tile 64, 256 threads.
// (unchanged from round 6)
// ============================================================================
#define QS_STRIDE 132
#define KS_STRIDE 132
#define VS_STRIDE 136
#define PS_STRIDE 68

#define ATTN_SMEM ((128*QS_STRIDE + 2*64*KS_STRIDE + 64*VS_STRIDE + 128*PS_STRIDE) * 4)

__global__ void __launch_bounds__(256) attn_kernel()
{
    extern __shared__ float smf[];
    float* Qs = smf;
    float* Ks = Qs + 128 * QS_STRIDE;
    float* Vs = Ks + 2 * 64 * KS_STRIDE;
    float* Ps = Vs + 64 * VS_STRIDE;

    const int tid  = threadIdx.x;
    const int lane = tid & 31;
    const int warp = tid >> 5;
    const int g = lane >> 2, t = lane & 3;

    const int qt = blockIdx.x;
    const int h  = blockIdx.y;
    const int b  = blockIdx.z;

    const size_t base = ((size_t)(b * NH + h)) << 18;
    const float* Qg = g_q + base + (size_t)qt * 128 * HD;
    const float* Kg = g_k + base;
    const float* Vg = g_v + base;

    const uint32_t sQ = (uint32_t)__cvta_generic_to_shared(Qs);
    const uint32_t sK = (uint32_t)__cvta_generic_to_shared(Ks);
    const uint32_t sV = (uint32_t)__cvta_generic_to_shared(Vs);

    const int lr = tid >> 3;
    const int lc = (tid & 7) * 4;

    #pragma unroll
    for (int i = 0; i < 4; i++) {
        int r = lr + i * 32;
        #pragma unroll
        for (int j = 0; j < 4; j++)
            cpa16(sQ + (uint32_t)(r * QS_STRIDE + j * 32 + lc) * 4u,
                  Qg + (size_t)r * HD + j * 32 + lc);
    }
    cpa_commit();

    #pragma unroll
    for (int i = 0; i < 2; i++) {
        int r = lr + i * 32;
        #pragma unroll
        for (int j = 0; j < 4; j++)
            cpa16(sK + (uint32_t)(r * KS_STRIDE + j * 32 + lc) * 4u,
                  Kg + (size_t)r * HD + j * 32 + lc);
    }
    cpa_commit();

    float o[16][4];
    #pragma unroll
    for (int ni = 0; ni < 16; ni++)
        #pragma unroll
        for (int j = 0; j < 4; j++) o[ni][j] = 0.f;

    const float NEGINF = -1e30f;
    float mrow0 = NEGINF, mrow1 = NEGINF;
    float lrow0 = 0.f,    lrow1 = 0.f;
    const float sl = 0.088388347648318447f * 1.4426950408889634f;

    const int qrow = warp * 16 + g;
    const int nkt = 2 * qt + 2;

    #pragma unroll 1
    for (int kt = 0; kt < nkt; kt++) {
        const int cur = kt & 1, nxt = cur ^ 1;

        {
            const float* Vg4 = Vg + (size_t)kt * 64 * HD;
            #pragma unroll
            for (int i = 0; i < 2; i++) {
                int r = lr + i * 32;
                #pragma unroll
                for (int j = 0; j < 4; j++)
                    cpa16(sV + (uint32_t)(r * VS_STRIDE + j * 32 + lc) * 4u,
                          Vg4 + (size_t)r * HD + j * 32 + lc);
            }
            cpa_commit();
        }
        if (kt + 1 < nkt) {
            const float* Kg4 = Kg + (size_t)(kt + 1) * 64 * HD;
            uint32_t bK = sK + (uint32_t)(nxt * 64 * KS_STRIDE) * 4u;
            #pragma unroll
            for (int i = 0; i < 2; i++) {
                int r = lr + i * 32;
                #pragma unroll
                for (int j = 0; j < 4; j++)
                    cpa16(bK + (uint32_t)(r * KS_STRIDE + j * 32 + lc) * 4u,
                          Kg4 + (size_t)r * HD + j * 32 + lc);
            }
        }
        cpa_commit();

        cpa_wait<2>();
        __syncthreads();

        const float* Kc = Ks + cur * 64 * KS_STRIDE;

        float s[8][4];
        #pragma unroll
        for (int ni = 0; ni < 8; ni++)
            #pragma unroll
            for (int j = 0; j < 4; j++) s[ni][j] = 0.f;

        #pragma unroll
        for (int kk = 0; kk < 16; kk++) {
            uint32_t a[4];
            a[0] = __float_as_uint(Qs[qrow       * QS_STRIDE + kk * 8 + t]);
            a[1] = __float_as_uint(Qs[(qrow + 8) * QS_STRIDE + kk * 8 + t]);
            a[2] = __float_as_uint(Qs[qrow       * QS_STRIDE + kk * 8 + t + 4]);
            a[3] = __float_as_uint(Qs[(qrow + 8) * QS_STRIDE + kk * 8 + t + 4]);
            #pragma unroll
            for (int ni = 0; ni < 8; ni++) {
                uint32_t bf[2];
                int kr = ni * 8 + g;
                bf[0] = __float_as_uint(Kc[kr * KS_STRIDE + kk * 8 + t]);
                bf[1] = __float_as_uint(Kc[kr * KS_STRIDE + kk * 8 + t + 4]);
                mma_m16n8k8(s[ni], a, bf);
            }
        }

        #pragma unroll
        for (int ni = 0; ni < 8; ni++)
            #pragma unroll
            for (int j = 0; j < 4; j++) s[ni][j] *= sl;

        if (kt >= 2 * qt) {
            int q0 = qt * 128 + qrow;
            #pragma unroll
            for (int ni = 0; ni < 8; ni++) {
                int kg = kt * 64 + ni * 8 + 2 * t;
                if (kg     > q0)     s[ni][0] = NEGINF;
                if (kg + 1 > q0)     s[ni][1] = NEGINF;
                if (kg     > q0 + 8) s[ni][2] = NEGINF;
                if (kg + 1 > q0 + 8) s[ni][3] = NEGINF;
            }
        }

        float mx0 = NEGINF, mx1 = NEGINF;
        #pragma unroll
        for (int ni = 0; ni < 8; ni++) {
            mx0 = fmaxf(mx0, fmaxf(s[ni][0], s[ni][1]));
            mx1 = fmaxf(mx1, fmaxf(s[ni][2], s[ni][3]));
        }
        mx0 = fmaxf(mx0, __shfl_xor_sync(0xffffffffu, mx0, 1));
        mx0 = fmaxf(mx0, __shfl_xor_sync(0xffffffffu, mx0, 2));
        mx1 = fmaxf(mx1, __shfl_xor_sync(0xffffffffu, mx1, 1));
        mx1 = fmaxf(mx1, __shfl_xor_sync(0xffffffffu, mx1, 2));

        float mn0 = fmaxf(mrow0, mx0), mn1 = fmaxf(mrow1, mx1);
        float al0 = exp2f(mrow0 - mn0), al1 = exp2f(mrow1 - mn1);
        mrow0 = mn0; mrow1 = mn1;

        float rs0 = 0.f, rs1 = 0.f;
        #pragma unroll
        for (int ni = 0; ni < 8; ni++) {
            s[ni][0] = exp2f(s[ni][0] - mn0); rs0 += s[ni][0];
            s[ni][1] = exp2f(s[ni][1] - mn0); rs0 += s[ni][1];
            s[ni][2] = exp2f(s[ni][2] - mn1); rs1 += s[ni][2];
            s[ni][3] = exp2f(s[ni][3] - mn1); rs1 += s[ni][3];
        }
        rs0 += __shfl_xor_sync(0xffffffffu, rs0, 1);
        rs0 += __shfl_xor_sync(0xffffffffu, rs0, 2);
        rs1 += __shfl_xor_sync(0xffffffffu, rs1, 1);
        rs1 += __shfl_xor_sync(0xffffffffu, rs1, 2);
        lrow0 = lrow0 * al0 + rs0;
        lrow1 = lrow1 * al1 + rs1;

        #pragma unroll
        for (int ni = 0; ni < 16; ni++) {
            o[ni][0] *= al0; o[ni][1] *= al0;
            o[ni][2] *= al1; o[ni][3] *= al1;
        }

        #pragma unroll
        for (int ni = 0; ni < 8; ni++) {
            int col = ni * 8 + 2 * t;
            Ps[qrow       * PS_STRIDE + col    ] = __uint_as_float(f2tf(s[ni][0]));
            Ps[qrow       * PS_STRIDE + col + 1] = __uint_as_float(f2tf(s[ni][1]));
            Ps[(qrow + 8) * PS_STRIDE + col    ] = __uint_as_float(f2tf(s[ni][2]));
            Ps[(qrow + 8) * PS_STRIDE + col + 1] = __uint_as_float(f2tf(s[ni][3]));
        }
        __syncwarp();

        cpa_wait<1>();
        __syncthreads();

        #pragma unroll
        for (int kc = 0; kc < 8; kc++) {
            uint32_t a[4];
            a[0] = __float_as_uint(Ps[qrow       * PS_STRIDE + kc * 8 + t]);
            a[1] = __float_as_uint(Ps[(qrow + 8) * PS_STRIDE + kc * 8 + t]);
            a[2] = __float_as_uint(Ps[qrow       * PS_STRIDE + kc * 8 + t + 4]);
            a[3] = __float_as_uint(Ps[(qrow + 8) * PS_STRIDE + kc * 8 + t + 4]);
            #pragma unroll
            for (int ni = 0; ni < 16; ni++) {
                uint32_t bf[2];
                bf[0] = __float_as_uint(Vs[(kc * 8 + t    ) * VS_STRIDE + ni * 8 + g]);
                bf[1] = __float_as_uint(Vs[(kc * 8 + t + 4) * VS_STRIDE + ni * 8 + g]);
                mma_m16n8k8(o[ni], a, bf);
            }
        }
        __syncthreads();
    }

    float i0 = 1.f / lrow0, i1 = 1.f / lrow1;
    int qg = qt * 128 + qrow;
    float* Og = g_o + ((size_t)(b * SS + qg)) * HH + h * HD;
    #pragma unroll
    for (int ni = 0; ni < 16; ni++) {
        int d = ni * 8 + 2 * t;
        float2 v0 = make_float2(__uint_as_float(f2tf(o[ni][0] * i0)),
                                __uint_as_float(f2tf(o[ni][1] * i0)));
        float2 v1 = make_float2(__uint_as_float(f2tf(o[ni][2] * i1)),
                                __uint_as_float(f2tf(o[ni][3] * i1)));
        *reinterpret_cast<float2*>(&Og[d])             = v0;
        *reinterpret_cast<float2*>(&Og[8ull * HH + d]) = v1;
    }
}

// ============================================================================
extern "C" void kernel_launch(void* const* d_in, const int* in_sizes, int n_in,
                              void* d_out, int out_size) {
    const float* x  = (const float*)d_in[0];
    const float* wq = (const float*)d_in[1];
    const float* wk = (const float*)d_in[2];
    const float* wv = (const float*)d_in[3];
    const float* wo = (const float*)d_in[4];
    float* out = (float*)d_out;

    float *q, *k, *v, *o, *xr, *wr;
    cudaGetSymbolAddress((void**)&q,  g_q);
    cudaGetSymbolAddress((void**)&k,  g_k);
    cudaGetSymbolAddress((void**)&v,  g_v);
    cudaGetSymbolAddress((void**)&o,  g_o);
    cudaGetSymbolAddress((void**)&xr, g_x);
    cudaGetSymbolAddress((void**)&wr, g_w);

    cudaFuncSetAttribute(gemm_tf32_kernel, cudaFuncAttributeMaxDynamicSharedMemorySize, GEMM_SMEM);
    cudaFuncSetAttribute(attn_kernel,      cudaFuncAttributeMaxDynamicSharedMemorySize, ATTN_SMEM);

    // pre-round inputs to tf32
    const int XN4 = MM * HH / 4;
    const int WN4 = HH * HH / 4;
    round_tf32_kernel<<<(XN4 + 255) / 256, 256>>>(x,  xr, XN4);
    round_tf32_kernel<<<(WN4 + 255) / 256, 256>>>(wq, wr + 0ull * HH * HH, WN4);
    round_tf32_kernel<<<(WN4 + 255) / 256, 256>>>(wk, wr + 1ull * HH * HH, WN4);
    round_tf32_kernel<<<(WN4 + 255) / 256, 256>>>(wv, wr + 2ull * HH * HH, WN4);
    round_tf32_kernel<<<(WN4 + 255) / 256, 256>>>(wo, wr + 3ull * HH * HH, WN4);

    dim3 gblk(256);

    // fused QKV: gridDim.z selects weight + destination
    gemm_tf32_kernel<<<dim3(HH / 128, MM / 128, 3), gblk, GEMM_SMEM>>>(
        xr, wr, q, k, v, 1);

    attn_kernel<<<dim3(SS / 128, NH, BB), 256, ATTN_SMEM>>>();

    // output projection: W = wr + 3*HH*HH (pass base offset so z=0 picks wo)
    gemm_tf32_kernel<<<dim3(HH / 128, MM / 128, 1), gblk, GEMM_SMEM>>>(
        o, wr + 3ull * HH * HH, out, out, out, 0);
}

// round 11
// speedup vs baseline: 1.3011x; 1.1562x over previous
#include <cuda_runtime.h>
#include <cstdint>

// Problem constants
#define BB 4
#define SS 2048
#define HH 2048
#define NH 16
#define HD 128
#define MM (BB*SS)            // 8192 rows

// Scratch (allocation-free: __device__ globals)
// g_x, g_w, g_o hold FRAGMENT-PACKED tf32 operands (see pack layout below).
// g_q/g_k/g_v hold row-major [b,h,s,d] tf32-rounded values for the attn kernel.
__device__ float g_q[BB*NH*SS*HD];
__device__ float g_k[BB*NH*SS*HD];
__device__ float g_v[BB*NH*SS*HD];
__device__ float g_o[MM*HH];         // packed A-operand for output GEMM
__device__ float g_x[MM*HH];         // packed A-operand for QKV GEMM
__device__ float g_w[4][HH*HH];      // packed B-operands (q,k,v,o)

__device__ __forceinline__ uint32_t f2tf(float f) {
    uint32_t u; asm("cvt.rna.tf32.f32 %0, %1;" : "=r"(u) : "f"(f)); return u;
}

__device__ __forceinline__ void mma_m16n8k8(float c[4], const uint32_t a[4], const uint32_t b[2]) {
    asm volatile(
        "mma.sync.aligned.m16n8k8.row.col.f32.tf32.tf32.f32 "
        "{%0,%1,%2,%3},{%4,%5,%6,%7},{%8,%9},{%0,%1,%2,%3};"
        : "+f"(c[0]), "+f"(c[1]), "+f"(c[2]), "+f"(c[3])
        : "r"(a[0]), "r"(a[1]), "r"(a[2]), "r"(a[3]), "r"(b[0]), "r"(b[1]));
}

__device__ __forceinline__ void cpa16(uint32_t s, const float* g) {
    asm volatile("cp.async.cg.shared.global [%0], [%1], 16;\n" :: "r"(s), "l"(g));
}
__device__ __forceinline__ void cpa_commit() {
    asm volatile("cp.async.commit_group;\n" ::: "memory");
}
template<int N> __device__ __forceinline__ void cpa_wait() {
    asm volatile("cp.async.wait_group %0;\n" :: "n"(N) : "memory");
}

// ============================================================================
// Packed operand layouts (K = 2048, BK = 32):
//   A-pack: [m_tile = M/128][k_tile = 64][m16 = 8][k8 = 4][lane = 32][4]
//     vector elems (lane = g*4+t): [ (g,t), (8+g,t), (g,t+4), (8+g,t+4) ]
//     (rows relative to 16-row block, cols relative to 8-col block)
//   B-pack: [n_tile = N/128][k_tile = 64][n16 = 8][k8 = 4][lane = 32][4]
//     vector elems: [ (g,t), (g,t+4), (8+g,t), (8+g,t+4) ]
// One (tile, k_tile) slab = 4096 floats = 16 KB, contiguous.
// ============================================================================

__global__ void pack_a_kernel(const float* __restrict__ in, float* __restrict__ out, int ntot) {
    int o = blockIdx.x * blockDim.x + threadIdx.x;
    if (o >= ntot) return;
    int lane = o & 31, k8 = (o >> 5) & 3, m16 = (o >> 7) & 7, kt = (o >> 10) & 63;
    int mt = o >> 16;
    int g = lane >> 2, t = lane & 3;
    size_t r0 = (size_t)mt * 128 + m16 * 16 + g;
    int c0 = kt * 32 + k8 * 8 + t;
    const float* p = in + r0 * HH + c0;
    float4 v;
    v.x = __uint_as_float(f2tf(p[0]));
    v.y = __uint_as_float(f2tf(p[8 * HH]));
    v.z = __uint_as_float(f2tf(p[4]));
    v.w = __uint_as_float(f2tf(p[8 * HH + 4]));
    reinterpret_cast<float4*>(out)[o] = v;
}

// 4 weights in one launch (blockIdx.y selects)
__global__ void pack_b_kernel(const float* __restrict__ w0, const float* __restrict__ w1,
                              const float* __restrict__ w2, const float* __restrict__ w3,
                              float* __restrict__ out, int ntot) {
    int o = blockIdx.x * blockDim.x + threadIdx.x;
    if (o >= ntot) return;
    int z = blockIdx.y;
    const float* in = (z == 0) ? w0 : (z == 1) ? w1 : (z == 2) ? w2 : w3;
    float* dst = out + (size_t)z * HH * HH;
    int lane = o & 31, k8 = (o >> 5) & 3, n16 = (o >> 7) & 7, kt = (o >> 10) & 63;
    int nt = o >> 16;
    int g = lane >> 2, t = lane & 3;
    size_t r0 = (size_t)nt * 128 + n16 * 16 + g;
    int c0 = kt * 32 + k8 * 8 + t;
    const float* p = in + r0 * HH + c0;
    float4 v;
    v.x = __uint_as_float(f2tf(p[0]));
    v.y = __uint_as_float(f2tf(p[4]));
    v.z = __uint_as_float(f2tf(p[8 * HH]));
    v.w = __uint_as_float(f2tf(p[8 * HH + 4]));
    reinterpret_cast<float4*>(dst)[o] = v;
}

// ============================================================================
// GEMM on packed operands: C[M,N] = A[M,K] * W[N,K]^T (tf32 mma,
// 128x128x32 tiles, 3-stage cp.async, LDS.128 fragment loads, 2 CTAs/SM).
// qkv_mode=1: W = Wpack + z*HH*HH, C = {Cq,Ck,Cv}[z], scatter+round to [b,h,s,d].
// qkv_mode=0: plain row-major C (z must be 0).
// ============================================================================
#define GSTG 3
#define STG_F 4096                       // floats per stage slab (16 KB)
#define GEMM_SMEM (GSTG * 2 * STG_F * 4) // 98304 bytes -> 2 CTAs/SM

__global__ void __launch_bounds__(256, 2) gemm_tf32_kernel(
    const float* __restrict__ Apack, const float* __restrict__ Wpack,
    float* __restrict__ Cq, float* __restrict__ Ck, float* __restrict__ Cv,
    int qkv_mode)
{
    const int N = HH;
    extern __shared__ float sm[];
    float* As = sm;                      // [GSTG][STG_F]
    float* Bs = sm + GSTG * STG_F;

    const int tid  = threadIdx.x;
    const int lane = tid & 31;
    const int warp = tid >> 5;
    const int g = lane >> 2, t = lane & 3;
    const int wm = warp & 3, wn = warp >> 2;     // 4 x 2 warp grid, warp tile 32x64
    const int mt = blockIdx.y;
    const int nt = blockIdx.x;
    const int z  = blockIdx.z;

    float* C = (z == 0) ? Cq : (z == 1) ? Ck : Cv;
    const float* Ab = Apack + ((size_t)mt * 64) * STG_F;
    const float* Bb = Wpack + (size_t)z * HH * HH + ((size_t)nt * 64) * STG_F;

    const uint32_t sA = (uint32_t)__cvta_generic_to_shared(As);
    const uint32_t sB = (uint32_t)__cvta_generic_to_shared(Bs);

    auto load_stage = [&](int s, int kt) {
        uint32_t bA = sA + (uint32_t)(s * STG_F) * 4u;
        uint32_t bB = sB + (uint32_t)(s * STG_F) * 4u;
        const float* pA = Ab + (size_t)kt * STG_F;
        const float* pB = Bb + (size_t)kt * STG_F;
        #pragma unroll
        for (int i = 0; i < 4; i++) {
            int off = i * 256 + tid;              // 16B granule index
            cpa16(bA + (uint32_t)off * 16u, pA + off * 4);
            cpa16(bB + (uint32_t)off * 16u, pB + off * 4);
        }
        cpa_commit();
    };

    float acc[2][8][4];
    #pragma unroll
    for (int mi = 0; mi < 2; mi++)
        #pragma unroll
        for (int ni = 0; ni < 8; ni++)
            #pragma unroll
            for (int j = 0; j < 4; j++) acc[mi][ni][j] = 0.f;

    load_stage(0, 0);
    load_stage(1, 1);
    cpa_wait<1>();
    __syncthreads();

    const int nk = 64;
    #pragma unroll 1
    for (int kt = 0; kt < nk; kt++) {
        const int cur = kt % GSTG;
        if (kt + 2 < nk) load_stage((kt + 2) % GSTG, kt + 2);
        else             cpa_commit();

        const float* Ac = As + cur * STG_F;
        const float* Bc = Bs + cur * STG_F;

        #pragma unroll
        for (int kk = 0; kk < 4; kk++) {
            float4 av0 = *reinterpret_cast<const float4*>(Ac + ((wm * 2 + 0) * 4 + kk) * 128 + lane * 4);
            float4 av1 = *reinterpret_cast<const float4*>(Ac + ((wm * 2 + 1) * 4 + kk) * 128 + lane * 4);
            uint32_t a0[4] = {__float_as_uint(av0.x), __float_as_uint(av0.y),
                              __float_as_uint(av0.z), __float_as_uint(av0.w)};
            uint32_t a1[4] = {__float_as_uint(av1.x), __float_as_uint(av1.y),
                              __float_as_uint(av1.z), __float_as_uint(av1.w)};
            #pragma unroll
            for (int j = 0; j < 4; j++) {
                float4 bv = *reinterpret_cast<const float4*>(Bc + ((wn * 4 + j) * 4 + kk) * 128 + lane * 4);
                uint32_t be[2] = {__float_as_uint(bv.x), __float_as_uint(bv.y)};
                uint32_t bo[2] = {__float_as_uint(bv.z), __float_as_uint(bv.w)};
                mma_m16n8k8(acc[0][2*j],     a0, be);
                mma_m16n8k8(acc[1][2*j],     a1, be);
                mma_m16n8k8(acc[0][2*j + 1], a0, bo);
                mma_m16n8k8(acc[1][2*j + 1], a1, bo);
            }
        }
        cpa_wait<1>();
        __syncthreads();
    }

    // epilogue
    const int rowBase = mt * 128;
    const int colBase = nt * 128;
    #pragma unroll
    for (int mi = 0; mi < 2; mi++) {
        int r0 = rowBase + wm * 32 + mi * 16 + g;
        #pragma unroll
        for (int ni = 0; ni < 8; ni++) {
            int cc = colBase + wn * 64 + ni * 8 + 2 * t;
            if (!qkv_mode) {
                float* dst = C + (size_t)r0 * N + cc;
                *reinterpret_cast<float2*>(dst)           = make_float2(acc[mi][ni][0], acc[mi][ni][1]);
                *reinterpret_cast<float2*>(dst + 8ull*N)  = make_float2(acc[mi][ni][2], acc[mi][ni][3]);
            } else {
                int bb2 = r0 >> 11;
                int ss2 = r0 & 2047;
                int hh2 = cc >> 7;
                int dd  = cc & 127;
                float* dst = C + (((size_t)(bb2 * NH + hh2)) << 18) + (size_t)ss2 * HD + dd;
                float2 v0 = make_float2(__uint_as_float(f2tf(acc[mi][ni][0])),
                                        __uint_as_float(f2tf(acc[mi][ni][1])));
                float2 v1 = make_float2(__uint_as_float(f2tf(acc[mi][ni][2])),
                                        __uint_as_float(f2tf(acc[mi][ni][3])));
                *reinterpret_cast<float2*>(dst)          = v0;
                *reinterpret_cast<float2*>(dst + 8 * HD) = v1;
            }
        }
    }
}

// ============================================================================
// Flash attention (causal), tf32 mma. Q tile 128, K/V tile 64, 256 threads.
// Epilogue writes g_o in PACKED A-operand layout for the output GEMM.
// ============================================================================
#define QS_STRIDE 132
#define KS_STRIDE 132
#define VS_STRIDE 136
#define PS_STRIDE 68

#define ATTN_SMEM ((128*QS_STRIDE + 2*64*KS_STRIDE + 64*VS_STRIDE + 128*PS_STRIDE) * 4)

__global__ void __launch_bounds__(256) attn_kernel()
{
    extern __shared__ float smf[];
    float* Qs = smf;
    float* Ks = Qs + 128 * QS_STRIDE;
    float* Vs = Ks + 2 * 64 * KS_STRIDE;
    float* Ps = Vs + 64 * VS_STRIDE;

    const int tid  = threadIdx.x;
    const int lane = tid & 31;
    const int warp = tid >> 5;
    const int g = lane >> 2, t = lane & 3;

    const int qt = blockIdx.x;
    const int h  = blockIdx.y;
    const int b  = blockIdx.z;

    const size_t base = ((size_t)(b * NH + h)) << 18;
    const float* Qg = g_q + base + (size_t)qt * 128 * HD;
    const float* Kg = g_k + base;
    const float* Vg = g_v + base;

    const uint32_t sQ = (uint32_t)__cvta_generic_to_shared(Qs);
    const uint32_t sK = (uint32_t)__cvta_generic_to_shared(Ks);
    const uint32_t sV = (uint32_t)__cvta_generic_to_shared(Vs);

    const int lr = tid >> 3;
    const int lc = (tid & 7) * 4;

    #pragma unroll
    for (int i = 0; i < 4; i++) {
        int r = lr + i * 32;
        #pragma unroll
        for (int j = 0; j < 4; j++)
            cpa16(sQ + (uint32_t)(r * QS_STRIDE + j * 32 + lc) * 4u,
                  Qg + (size_t)r * HD + j * 32 + lc);
    }
    cpa_commit();

    #pragma unroll
    for (int i = 0; i < 2; i++) {
        int r = lr + i * 32;
        #pragma unroll
        for (int j = 0; j < 4; j++)
            cpa16(sK + (uint32_t)(r * KS_STRIDE + j * 32 + lc) * 4u,
                  Kg + (size_t)r * HD + j * 32 + lc);
    }
    cpa_commit();

    float o[16][4];
    #pragma unroll
    for (int ni = 0; ni < 16; ni++)
        #pragma unroll
        for (int j = 0; j < 4; j++) o[ni][j] = 0.f;

    const float NEGINF = -1e30f;
    float mrow0 = NEGINF, mrow1 = NEGINF;
    float lrow0 = 0.f,    lrow1 = 0.f;
    const float sl = 0.088388347648318447f * 1.4426950408889634f;

    const int qrow = warp * 16 + g;
    const int nkt = 2 * qt + 2;

    #pragma unroll 1
    for (int kt = 0; kt < nkt; kt++) {
        const int cur = kt & 1, nxt = cur ^ 1;

        {
            const float* Vg4 = Vg + (size_t)kt * 64 * HD;
            #pragma unroll
            for (int i = 0; i < 2; i++) {
                int r = lr + i * 32;
                #pragma unroll
                for (int j = 0; j < 4; j++)
                    cpa16(sV + (uint32_t)(r * VS_STRIDE + j * 32 + lc) * 4u,
                          Vg4 + (size_t)r * HD + j * 32 + lc);
            }
            cpa_commit();
        }
        if (kt + 1 < nkt) {
            const float* Kg4 = Kg + (size_t)(kt + 1) * 64 * HD;
            uint32_t bK = sK + (uint32_t)(nxt * 64 * KS_STRIDE) * 4u;
            #pragma unroll
            for (int i = 0; i < 2; i++) {
                int r = lr + i * 32;
                #pragma unroll
                for (int j = 0; j < 4; j++)
                    cpa16(bK + (uint32_t)(r * KS_STRIDE + j * 32 + lc) * 4u,
                          Kg4 + (size_t)r * HD + j * 32 + lc);
            }
        }
        cpa_commit();

        cpa_wait<2>();
        __syncthreads();

        const float* Kc = Ks + cur * 64 * KS_STRIDE;

        float s[8][4];
        #pragma unroll
        for (int ni = 0; ni < 8; ni++)
            #pragma unroll
            for (int j = 0; j < 4; j++) s[ni][j] = 0.f;

        #pragma unroll
        for (int kk = 0; kk < 16; kk++) {
            uint32_t a[4];
            a[0] = __float_as_uint(Qs[qrow       * QS_STRIDE + kk * 8 + t]);
            a[1] = __float_as_uint(Qs[(qrow + 8) * QS_STRIDE + kk * 8 + t]);
            a[2] = __float_as_uint(Qs[qrow       * QS_STRIDE + kk * 8 + t + 4]);
            a[3] = __float_as_uint(Qs[(qrow + 8) * QS_STRIDE + kk * 8 + t + 4]);
            #pragma unroll
            for (int ni = 0; ni < 8; ni++) {
                uint32_t bf[2];
                int kr = ni * 8 + g;
                bf[0] = __float_as_uint(Kc[kr * KS_STRIDE + kk * 8 + t]);
                bf[1] = __float_as_uint(Kc[kr * KS_STRIDE + kk * 8 + t + 4]);
                mma_m16n8k8(s[ni], a, bf);
            }
        }

        #pragma unroll
        for (int ni = 0; ni < 8; ni++)
            #pragma unroll
            for (int j = 0; j < 4; j++) s[ni][j] *= sl;

        if (kt >= 2 * qt) {
            int q0 = qt * 128 + qrow;
            #pragma unroll
            for (int ni = 0; ni < 8; ni++) {
                int kg = kt * 64 + ni * 8 + 2 * t;
                if (kg     > q0)     s[ni][0] = NEGINF;
                if (kg + 1 > q0)     s[ni][1] = NEGINF;
                if (kg     > q0 + 8) s[ni][2] = NEGINF;
                if (kg + 1 > q0 + 8) s[ni][3] = NEGINF;
            }
        }

        float mx0 = NEGINF, mx1 = NEGINF;
        #pragma unroll
        for (int ni = 0; ni < 8; ni++) {
            mx0 = fmaxf(mx0, fmaxf(s[ni][0], s[ni][1]));
            mx1 = fmaxf(mx1, fmaxf(s[ni][2], s[ni][3]));
        }
        mx0 = fmaxf(mx0, __shfl_xor_sync(0xffffffffu, mx0, 1));
        mx0 = fmaxf(mx0, __shfl_xor_sync(0xffffffffu, mx0, 2));
        mx1 = fmaxf(mx1, __shfl_xor_sync(0xffffffffu, mx1, 1));
        mx1 = fmaxf(mx1, __shfl_xor_sync(0xffffffffu, mx1, 2));

        float mn0 = fmaxf(mrow0, mx0), mn1 = fmaxf(mrow1, mx1);
        float al0 = exp2f(mrow0 - mn0), al1 = exp2f(mrow1 - mn1);
        mrow0 = mn0; mrow1 = mn1;

        float rs0 = 0.f, rs1 = 0.f;
        #pragma unroll
        for (int ni = 0; ni < 8; ni++) {
            s[ni][0] = exp2f(s[ni][0] - mn0); rs0 += s[ni][0];
            s[ni][1] = exp2f(s[ni][1] - mn0); rs0 += s[ni][1];
            s[ni][2] = exp2f(s[ni][2] - mn1); rs1 += s[ni][2];
            s[ni][3] = exp2f(s[ni][3] - mn1); rs1 += s[ni][3];
        }
        rs0 += __shfl_xor_sync(0xffffffffu, rs0, 1);
        rs0 += __shfl_xor_sync(0xffffffffu, rs0, 2);
        rs1 += __shfl_xor_sync(0xffffffffu, rs1, 1);
        rs1 += __shfl_xor_sync(0xffffffffu, rs1, 2);
        lrow0 = lrow0 * al0 + rs0;
        lrow1 = lrow1 * al1 + rs1;

        #pragma unroll
        for (int ni = 0; ni < 16; ni++) {
            o[ni][0] *= al0; o[ni][1] *= al0;
            o[ni][2] *= al1; o[ni][3] *= al1;
        }

        #pragma unroll
        for (int ni = 0; ni < 8; ni++) {
            int col = ni * 8 + 2 * t;
            Ps[qrow       * PS_STRIDE + col    ] = __uint_as_float(f2tf(s[ni][0]));
            Ps[qrow       * PS_STRIDE + col + 1] = __uint_as_float(f2tf(s[ni][1]));
            Ps[(qrow + 8) * PS_STRIDE + col    ] = __uint_as_float(f2tf(s[ni][2]));
            Ps[(qrow + 8) * PS_STRIDE + col + 1] = __uint_as_float(f2tf(s[ni][3]));
        }
        __syncwarp();

        cpa_wait<1>();
        __syncthreads();

        #pragma unroll
        for (int kc = 0; kc < 8; kc++) {
            uint32_t a[4];
            a[0] = __float_as_uint(Ps[qrow       * PS_STRIDE + kc * 8 + t]);
            a[1] = __float_as_uint(Ps[(qrow + 8) * PS_STRIDE + kc * 8 + t]);
            a[2] = __float_as_uint(Ps[qrow       * PS_STRIDE + kc * 8 + t + 4]);
            a[3] = __float_as_uint(Ps[(qrow + 8) * PS_STRIDE + kc * 8 + t + 4]);
            #pragma unroll
            for (int ni = 0; ni < 16; ni++) {
                uint32_t bf[2];
                bf[0] = __float_as_uint(Vs[(kc * 8 + t    ) * VS_STRIDE + ni * 8 + g]);
                bf[1] = __float_as_uint(Vs[(kc * 8 + t + 4) * VS_STRIDE + ni * 8 + g]);
                mma_m16n8k8(o[ni], a, bf);
            }
        }
        __syncthreads();
    }

    // normalize + tf32-round + store O in PACKED A-operand layout:
    // addr(floats) = (((m_tile*64 + k_tile)*8 + m16)*4 + k8)*128 + lane'*4 + elem
    // m = b*SS + qt*128 + qrow(+8): m_tile = b*16+qt, m16 = warp, g' = g,
    //   mhi = 0 for qrow rows, 1 for qrow+8 rows
    // c = h*HD + ni*8 + 2t(+1): k_tile = h*4 + (ni>>2), k8 = ni&3,
    //   t' = c&3, chi = (c>>2)&1, elem = chi*2 + mhi, lane' = g*4 + t'
    {
        float i0 = 1.f / lrow0, i1 = 1.f / lrow1;
        const int m_tile = b * 16 + qt;
        const int m16 = warp;
        const int tl0 = (2 * t) & 3,     hi0 = (2 * t) >> 2;
        const int tl1 = (2 * t + 1) & 3, hi1 = (2 * t + 1) >> 2;
        #pragma unroll
        for (int ni = 0; ni < 16; ni++) {
            int k_tile = h * 4 + (ni >> 2);
            int k8 = ni & 3;
            size_t blk = ((((size_t)m_tile * 64 + k_tile) * 8 + m16) * 4 + k8) * 128;
            g_o[blk + (g * 4 + tl0) * 4 + hi0 * 2 + 0] = __uint_as_float(f2tf(o[ni][0] * i0));
            g_o[blk + (g * 4 + tl1) * 4 + hi1 * 2 + 0] = __uint_as_float(f2tf(o[ni][1] * i0));
            g_o[blk + (g * 4 + tl0) * 4 + hi0 * 2 + 1] = __uint_as_float(f2tf(o[ni][2] * i1));
            g_o[blk + (g * 4 + tl1) * 4 + hi1 * 2 + 1] = __uint_as_float(f2tf(o[ni][3] * i1));
        }
    }
}

// ============================================================================
extern "C" void kernel_launch(void* const* d_in, const int* in_sizes, int n_in,
                              void* d_out, int out_size) {
    const float* x  = (const float*)d_in[0];
    const float* wq = (const float*)d_in[1];
    const float* wk = (const float*)d_in[2];
    const float* wv = (const float*)d_in[3];
    const float* wo = (const float*)d_in[4];
    float* out = (float*)d_out;

    float *q, *k, *v, *o, *xr, *wr;
    cudaGetSymbolAddress((void**)&q,  g_q);
    cudaGetSymbolAddress((void**)&k,  g_k);
    cudaGetSymbolAddress((void**)&v,  g_v);
    cudaGetSymbolAddress((void**)&o,  g_o);
    cudaGetSymbolAddress((void**)&xr, g_x);
    cudaGetSymbolAddress((void**)&wr, g_w);

    cudaFuncSetAttribute(gemm_tf32_kernel, cudaFuncAttributeMaxDynamicSharedMemorySize, GEMM_SMEM);
    cudaFuncSetAttribute(attn_kernel,      cudaFuncAttributeMaxDynamicSharedMemorySize, ATTN_SMEM);

    // pack + tf32-round inputs
    const int XV = MM * HH / 4;   // 4,194,304 vectors
    const int WV = HH * HH / 4;   // 1,048,576 vectors
    pack_a_kernel<<<(XV + 255) / 256, 256>>>(x, xr, XV);
    pack_b_kernel<<<dim3((WV + 255) / 256, 4), 256>>>(wq, wk, wv, wo, wr, WV);

    dim3 gblk(256);

    // fused QKV: gridDim.z selects weight + destination
    gemm_tf32_kernel<<<dim3(HH / 128, MM / 128, 3), gblk, GEMM_SMEM>>>(
        xr, wr, q, k, v, 1);

    attn_kernel<<<dim3(SS / 128, NH, BB), 256, ATTN_SMEM>>>();

    // output projection (A = packed g_o, W = packed wo at offset 3)
    gemm_tf32_kernel<<<dim3(HH / 128, MM / 128, 1), gblk, GEMM_SMEM>>>(
        o, wr + 3ull * HH * HH, out, out, out, 0);
}

// round 12
// speedup vs baseline: 1.4006x; 1.0765x over previous
#include <cuda_runtime.h>
#include <cstdint>

// Problem constants
#define BB 4
#define SS 2048
#define HH 2048
#define NH 16
#define HD 128
#define MM (BB*SS)            // 8192 rows

// Scratch (allocation-free: __device__ globals)
// ALL tensors live in fragment-packed tf32 layouts:
//   A-pack (per 128-row x 2048-col matrix): [m_tile][k_tile=64][m16=8][k8=4][lane][4]
//     vector elems (lane=g*4+t): [ (g,t), (8+g,t), (g,t+4), (8+g,t+4) ]
//   B-pack: same shape, elems [ (g,t), (g,t+4), (8+g,t), (8+g,t+4) ]
// g_q: per (b,h): [qt=16][m16=8][k8=16][lane][4]      (A-operand, 16384 f/tile)
// g_k: per (b,h): [kt=32][n16=4][k8=16][lane][4]      (B-operand, 8192 f/tile)
// g_v: per (b,h): [kt=32][n16=8][k8=8][lane][4]       (B-op, n=headdim k=seq)
// g_o: packed A-operand for output GEMM; g_x packed A; g_w packed B x4.
__device__ float g_q[BB*NH*SS*HD];
__device__ float g_k[BB*NH*SS*HD];
__device__ float g_v[BB*NH*SS*HD];
__device__ float g_o[MM*HH];
__device__ float g_x[MM*HH];
__device__ float g_w[4][HH*HH];

__device__ __forceinline__ uint32_t f2tf(float f) {
    uint32_t u; asm("cvt.rna.tf32.f32 %0, %1;" : "=r"(u) : "f"(f)); return u;
}
__device__ __forceinline__ float rndtf(float f) { return __uint_as_float(f2tf(f)); }

__device__ __forceinline__ void mma_m16n8k8(float c[4], const uint32_t a[4], const uint32_t b[2]) {
    asm volatile(
        "mma.sync.aligned.m16n8k8.row.col.f32.tf32.tf32.f32 "
        "{%0,%1,%2,%3},{%4,%5,%6,%7},{%8,%9},{%0,%1,%2,%3};"
        : "+f"(c[0]), "+f"(c[1]), "+f"(c[2]), "+f"(c[3])
        : "r"(a[0]), "r"(a[1]), "r"(a[2]), "r"(a[3]), "r"(b[0]), "r"(b[1]));
}

__device__ __forceinline__ void cpa16(uint32_t s, const float* g) {
    asm volatile("cp.async.cg.shared.global [%0], [%1], 16;\n" :: "r"(s), "l"(g));
}
__device__ __forceinline__ void cpa_commit() {
    asm volatile("cp.async.commit_group;\n" ::: "memory");
}
template<int N> __device__ __forceinline__ void cpa_wait() {
    asm volatile("cp.async.wait_group %0;\n" :: "n"(N) : "memory");
}

// ============================================================================
// Input packing kernels (tf32-round + fragment layout)
// ============================================================================
__global__ void pack_a_kernel(const float* __restrict__ in, float* __restrict__ out, int ntot) {
    int o = blockIdx.x * blockDim.x + threadIdx.x;
    if (o >= ntot) return;
    int lane = o & 31, k8 = (o >> 5) & 3, m16 = (o >> 7) & 7, kt = (o >> 10) & 63;
    int mt = o >> 16;
    int g = lane >> 2, t = lane & 3;
    size_t r0 = (size_t)mt * 128 + m16 * 16 + g;
    int c0 = kt * 32 + k8 * 8 + t;
    const float* p = in + r0 * HH + c0;
    float4 v;
    v.x = rndtf(p[0]);
    v.y = rndtf(p[8 * HH]);
    v.z = rndtf(p[4]);
    v.w = rndtf(p[8 * HH + 4]);
    reinterpret_cast<float4*>(out)[o] = v;
}

__global__ void pack_b_kernel(const float* __restrict__ w0, const float* __restrict__ w1,
                              const float* __restrict__ w2, const float* __restrict__ w3,
                              float* __restrict__ out, int ntot) {
    int o = blockIdx.x * blockDim.x + threadIdx.x;
    if (o >= ntot) return;
    int z = blockIdx.y;
    const float* in = (z == 0) ? w0 : (z == 1) ? w1 : (z == 2) ? w2 : w3;
    float* dst = out + (size_t)z * HH * HH;
    int lane = o & 31, k8 = (o >> 5) & 3, n16 = (o >> 7) & 7, kt = (o >> 10) & 63;
    int nt = o >> 16;
    int g = lane >> 2, t = lane & 3;
    size_t r0 = (size_t)nt * 128 + n16 * 16 + g;
    int c0 = kt * 32 + k8 * 8 + t;
    const float* p = in + r0 * HH + c0;
    float4 v;
    v.x = rndtf(p[0]);
    v.y = rndtf(p[4]);
    v.z = rndtf(p[8 * HH]);
    v.w = rndtf(p[8 * HH + 4]);
    reinterpret_cast<float4*>(dst)[o] = v;
}

// ============================================================================
// GEMM on packed operands (tf32 mma, 128x128x32 tiles, 3-stage cp.async,
// LDS.128 fragment loads, 2 CTAs/SM).
// qkv_mode=1: epilogue writes Q (A-pack), K (B-pack), V (B-pack, n=d/k=s)
// per-(b,h) tiles. qkv_mode=0: plain row-major C.
// ============================================================================
#define GSTG 3
#define STG_F 4096
#define GEMM_SMEM (GSTG * 2 * STG_F * 4) // 98304 bytes

__global__ void __launch_bounds__(256, 2) gemm_tf32_kernel(
    const float* __restrict__ Apack, const float* __restrict__ Wpack,
    float* __restrict__ Cq, float* __restrict__ Ck, float* __restrict__ Cv,
    int qkv_mode)
{
    const int N = HH;
    extern __shared__ float sm[];
    float* As = sm;
    float* Bs = sm + GSTG * STG_F;

    const int tid  = threadIdx.x;
    const int lane = tid & 31;
    const int warp = tid >> 5;
    const int g = lane >> 2, t = lane & 3;
    const int wm = warp & 3, wn = warp >> 2;
    const int mt = blockIdx.y;
    const int nt = blockIdx.x;
    const int z  = blockIdx.z;

    float* C = (z == 0) ? Cq : (z == 1) ? Ck : Cv;
    const float* Ab = Apack + ((size_t)mt * 64) * STG_F;
    const float* Bb = Wpack + (size_t)z * HH * HH + ((size_t)nt * 64) * STG_F;

    const uint32_t sA = (uint32_t)__cvta_generic_to_shared(As);
    const uint32_t sB = (uint32_t)__cvta_generic_to_shared(Bs);

    auto load_stage = [&](int s, int kt) {
        uint32_t bA = sA + (uint32_t)(s * STG_F) * 4u;
        uint32_t bB = sB + (uint32_t)(s * STG_F) * 4u;
        const float* pA = Ab + (size_t)kt * STG_F;
        const float* pB = Bb + (size_t)kt * STG_F;
        #pragma unroll
        for (int i = 0; i < 4; i++) {
            int off = i * 256 + tid;
            cpa16(bA + (uint32_t)off * 16u, pA + off * 4);
            cpa16(bB + (uint32_t)off * 16u, pB + off * 4);
        }
        cpa_commit();
    };

    float acc[2][8][4];
    #pragma unroll
    for (int mi = 0; mi < 2; mi++)
        #pragma unroll
        for (int ni = 0; ni < 8; ni++)
            #pragma unroll
            for (int j = 0; j < 4; j++) acc[mi][ni][j] = 0.f;

    load_stage(0, 0);
    load_stage(1, 1);
    cpa_wait<1>();
    __syncthreads();

    const int nk = 64;
    #pragma unroll 1
    for (int kt = 0; kt < nk; kt++) {
        const int cur = kt % GSTG;
        if (kt + 2 < nk) load_stage((kt + 2) % GSTG, kt + 2);
        else             cpa_commit();

        const float* Ac = As + cur * STG_F;
        const float* Bc = Bs + cur * STG_F;

        #pragma unroll
        for (int kk = 0; kk < 4; kk++) {
            float4 av0 = *reinterpret_cast<const float4*>(Ac + ((wm * 2 + 0) * 4 + kk) * 128 + lane * 4);
            float4 av1 = *reinterpret_cast<const float4*>(Ac + ((wm * 2 + 1) * 4 + kk) * 128 + lane * 4);
            uint32_t a0[4] = {__float_as_uint(av0.x), __float_as_uint(av0.y),
                              __float_as_uint(av0.z), __float_as_uint(av0.w)};
            uint32_t a1[4] = {__float_as_uint(av1.x), __float_as_uint(av1.y),
                              __float_as_uint(av1.z), __float_as_uint(av1.w)};
            #pragma unroll
            for (int j = 0; j < 4; j++) {
                float4 bv = *reinterpret_cast<const float4*>(Bc + ((wn * 4 + j) * 4 + kk) * 128 + lane * 4);
                uint32_t be[2] = {__float_as_uint(bv.x), __float_as_uint(bv.y)};
                uint32_t bo[2] = {__float_as_uint(bv.z), __float_as_uint(bv.w)};
                mma_m16n8k8(acc[0][2*j],     a0, be);
                mma_m16n8k8(acc[1][2*j],     a1, be);
                mma_m16n8k8(acc[0][2*j + 1], a0, bo);
                mma_m16n8k8(acc[1][2*j + 1], a1, bo);
            }
        }
        cpa_wait<1>();
        __syncthreads();
    }

    // epilogue
    const int rowBase = mt * 128;
    const int colBase = nt * 128;
    #pragma unroll
    for (int mi = 0; mi < 2; mi++) {
        int r0 = rowBase + wm * 32 + mi * 16 + g;
        #pragma unroll
        for (int ni = 0; ni < 8; ni++) {
            int cc = colBase + wn * 64 + ni * 8 + 2 * t;
            if (!qkv_mode) {
                float* dst = C + (size_t)r0 * N + cc;
                *reinterpret_cast<float2*>(dst)           = make_float2(acc[mi][ni][0], acc[mi][ni][1]);
                *reinterpret_cast<float2*>(dst + 8ull*N)  = make_float2(acc[mi][ni][2], acc[mi][ni][3]);
            } else {
                int b2 = r0 >> 11, s = r0 & 2047;
                int h2 = cc >> 7, d = cc & 127;
                int c8 = d & 7;                         // even (=2t)
                int tpa = c8 & 3, tpb = (c8 + 1) & 3, ca = c8 >> 2;
                float v0 = rndtf(acc[mi][ni][0]);
                float v1 = rndtf(acc[mi][ni][1]);
                float v2 = rndtf(acc[mi][ni][2]);
                float v3 = rndtf(acc[mi][ni][3]);
                if (z == 0) {
                    // Q: A-pack per (b,h): [qt][m16][k8=16][128]
                    int qt2 = s >> 7, sr = s & 127;
                    float* dst = Cq + (((size_t)((b2*NH + h2)*16 + qt2)) << 14)
                               + ((sr >> 4) * 16 + (d >> 3)) * 128 + g * 16;
                    dst[tpa*4 + ca*2]     = v0;   // elem = chi*2 + rhi
                    dst[tpb*4 + ca*2]     = v1;
                    dst[tpa*4 + ca*2 + 1] = v2;
                    dst[tpb*4 + ca*2 + 1] = v3;
                } else if (z == 1) {
                    // K: B-pack per (b,h): [kt][n16=4][k8=16][128]
                    int kt2 = s >> 6, nr = s & 63;
                    float* dst = Ck + (((size_t)((b2*NH + h2)*32 + kt2)) << 13)
                               + ((nr >> 4) * 16 + (d >> 3)) * 128 + g * 16;
                    dst[tpa*4 + ca]       = v0;   // elem = nhi*2 + chi
                    dst[tpb*4 + ca]       = v1;
                    dst[tpa*4 + 2 + ca]   = v2;
                    dst[tpb*4 + 2 + ca]   = v3;
                } else {
                    // V: B-pack with n=d, k=s per (b,h): [kt][n16=8][k8=8][128]
                    int kt2 = s >> 6, sk = s & 63;
                    int k8a = sk >> 3;              // r0+8 -> k8a+1 (ck=g both)
                    int tpk = g & 3, chk = g >> 2;
                    int gp = d & 7, nhi = (d >> 3) & 1;
                    float* dst = Cv + (((size_t)((b2*NH + h2)*32 + kt2)) << 13)
                               + ((d >> 4) * 8 + k8a) * 128;
                    int la = (gp*4 + tpk)*4 + nhi*2 + chk;
                    int lb = la + 16;               // col d+1 -> gp+1
                    dst[la]       = v0;
                    dst[lb]       = v1;
                    dst[128 + la] = v2;
                    dst[128 + lb] = v3;
                }
            }
        }
    }
}

// ============================================================================
// Flash attention (causal), tf32 mma, ALL fragment-packed operands.
// Q tile 128 (A-pack smem), K tile 64 double-buffered (B-pack), V tile 64
// (B-pack n=d), P written to A-pack smem. 256 threads.
// ============================================================================
#define AQ_OFF 0          // 16384 floats
#define AK_OFF 16384      // 2 x 8192
#define AV_OFF 32768      // 8192
#define AP_OFF 40960      // 8192
#define ATTN_SMEM (49152 * 4)   // 196608 bytes

__global__ void __launch_bounds__(256) attn_kernel()
{
    extern __shared__ float smf[];
    float* Qs = smf + AQ_OFF;
    float* Ks = smf + AK_OFF;
    float* Vs = smf + AV_OFF;
    float* Ps = smf + AP_OFF;

    const int tid  = threadIdx.x;
    const int lane = tid & 31;
    const int warp = tid >> 5;
    const int g = lane >> 2, t = lane & 3;

    const int qt = blockIdx.x;
    const int h  = blockIdx.y;
    const int b  = blockIdx.z;

    const float* Qg = g_q + (((size_t)((b*NH + h)*16 + qt)) << 14);
    const float* Kg = g_k + (((size_t)(b*NH + h)) << 18);
    const float* Vg = g_v + (((size_t)(b*NH + h)) << 18);

    const uint32_t sQ = (uint32_t)__cvta_generic_to_shared(Qs);
    const uint32_t sK = (uint32_t)__cvta_generic_to_shared(Ks);
    const uint32_t sV = (uint32_t)__cvta_generic_to_shared(Vs);

    // Q: 4096 x 16B, linear  (group 1)
    #pragma unroll
    for (int i = 0; i < 16; i++) {
        int off = i * 256 + tid;
        cpa16(sQ + (uint32_t)off * 16u, Qg + off * 4);
    }
    cpa_commit();

    // K tile 0  (group 2)
    #pragma unroll
    for (int i = 0; i < 8; i++) {
        int off = i * 256 + tid;
        cpa16(sK + (uint32_t)off * 16u, Kg + off * 4);
    }
    cpa_commit();

    float o[16][4];
    #pragma unroll
    for (int ni = 0; ni < 16; ni++)
        #pragma unroll
        for (int j = 0; j < 4; j++) o[ni][j] = 0.f;

    const float NEGINF = -1e30f;
    float mrow0 = NEGINF, mrow1 = NEGINF;
    float lrow0 = 0.f,    lrow1 = 0.f;
    const float sl = 0.088388347648318447f * 1.4426950408889634f;  // 1/sqrt(128)*log2e

    const int qrow = warp * 16 + g;
    const int nkt = 2 * qt + 2;

    #pragma unroll 1
    for (int kt = 0; kt < nkt; kt++) {
        const int cur = kt & 1, nxt = cur ^ 1;

        // V[kt] (single buffer; prev PV protected by trailing sync)
        {
            const float* Vt = Vg + (size_t)kt * 8192;
            #pragma unroll
            for (int i = 0; i < 8; i++) {
                int off = i * 256 + tid;
                cpa16(sV + (uint32_t)off * 16u, Vt + off * 4);
            }
            cpa_commit();
        }
        // K[kt+1]
        if (kt + 1 < nkt) {
            const float* Kt = Kg + (size_t)(kt + 1) * 8192;
            uint32_t bK = sK + (uint32_t)(nxt * 8192) * 4u;
            #pragma unroll
            for (int i = 0; i < 8; i++) {
                int off = i * 256 + tid;
                cpa16(bK + (uint32_t)off * 16u, Kt + off * 4);
            }
        }
        cpa_commit();

        cpa_wait<2>();          // Q + K[cur] ready
        __syncthreads();

        const float* Kc = Ks + cur * 8192;

        // S = Q K^T (warp tile 16x64), fully LDS.128
        float s[8][4];
        #pragma unroll
        for (int ni = 0; ni < 8; ni++)
            #pragma unroll
            for (int j = 0; j < 4; j++) s[ni][j] = 0.f;

        #pragma unroll
        for (int kk = 0; kk < 16; kk++) {
            float4 av = *reinterpret_cast<const float4*>(Qs + (warp * 16 + kk) * 128 + lane * 4);
            uint32_t a[4] = {__float_as_uint(av.x), __float_as_uint(av.y),
                             __float_as_uint(av.z), __float_as_uint(av.w)};
            #pragma unroll
            for (int nb = 0; nb < 4; nb++) {
                float4 bv = *reinterpret_cast<const float4*>(Kc + (nb * 16 + kk) * 128 + lane * 4);
                uint32_t be[2] = {__float_as_uint(bv.x), __float_as_uint(bv.y)};
                uint32_t bo[2] = {__float_as_uint(bv.z), __float_as_uint(bv.w)};
                mma_m16n8k8(s[2*nb],     a, be);
                mma_m16n8k8(s[2*nb + 1], a, bo);
            }
        }

        #pragma unroll
        for (int ni = 0; ni < 8; ni++)
            #pragma unroll
            for (int j = 0; j < 4; j++) s[ni][j] *= sl;

        // causal mask
        if (kt >= 2 * qt) {
            int q0 = qt * 128 + qrow;
            #pragma unroll
            for (int ni = 0; ni < 8; ni++) {
                int kg = kt * 64 + ni * 8 + 2 * t;
                if (kg     > q0)     s[ni][0] = NEGINF;
                if (kg + 1 > q0)     s[ni][1] = NEGINF;
                if (kg     > q0 + 8) s[ni][2] = NEGINF;
                if (kg + 1 > q0 + 8) s[ni][3] = NEGINF;
            }
        }

        // online softmax
        float mx0 = NEGINF, mx1 = NEGINF;
        #pragma unroll
        for (int ni = 0; ni < 8; ni++) {
            mx0 = fmaxf(mx0, fmaxf(s[ni][0], s[ni][1]));
            mx1 = fmaxf(mx1, fmaxf(s[ni][2], s[ni][3]));
        }
        mx0 = fmaxf(mx0, __shfl_xor_sync(0xffffffffu, mx0, 1));
        mx0 = fmaxf(mx0, __shfl_xor_sync(0xffffffffu, mx0, 2));
        mx1 = fmaxf(mx1, __shfl_xor_sync(0xffffffffu, mx1, 1));
        mx1 = fmaxf(mx1, __shfl_xor_sync(0xffffffffu, mx1, 2));

        float mn0 = fmaxf(mrow0, mx0), mn1 = fmaxf(mrow1, mx1);
        float al0 = exp2f(mrow0 - mn0), al1 = exp2f(mrow1 - mn1);
        mrow0 = mn0; mrow1 = mn1;

        float rs0 = 0.f, rs1 = 0.f;
        #pragma unroll
        for (int ni = 0; ni < 8; ni++) {
            s[ni][0] = exp2f(s[ni][0] - mn0); rs0 += s[ni][0];
            s[ni][1] = exp2f(s[ni][1] - mn0); rs0 += s[ni][1];
            s[ni][2] = exp2f(s[ni][2] - mn1); rs1 += s[ni][2];
            s[ni][3] = exp2f(s[ni][3] - mn1); rs1 += s[ni][3];
        }
        rs0 += __shfl_xor_sync(0xffffffffu, rs0, 1);
        rs0 += __shfl_xor_sync(0xffffffffu, rs0, 2);
        rs1 += __shfl_xor_sync(0xffffffffu, rs1, 1);
        rs1 += __shfl_xor_sync(0xffffffffu, rs1, 2);
        lrow0 = lrow0 * al0 + rs0;
        lrow1 = lrow1 * al1 + rs1;

        #pragma unroll
        for (int ni = 0; ni < 16; ni++) {
            o[ni][0] *= al0; o[ni][1] *= al0;
            o[ni][2] *= al1; o[ni][3] *= al1;
        }

        // write P (tf32) to A-pack smem; warp-private region
        {
            const int c8 = 2 * t;
            const int tpa = c8 & 3, tpb = (c8 + 1) & 3, ca = c8 >> 2;
            #pragma unroll
            for (int ni = 0; ni < 8; ni++) {
                float* dp = Ps + (warp * 8 + ni) * 128 + g * 16;
                dp[tpa*4 + ca*2]     = rndtf(s[ni][0]);   // elem = chi*2 + rhi
                dp[tpb*4 + ca*2]     = rndtf(s[ni][1]);
                dp[tpa*4 + ca*2 + 1] = rndtf(s[ni][2]);
                dp[tpb*4 + ca*2 + 1] = rndtf(s[ni][3]);
            }
        }
        __syncwarp();

        cpa_wait<1>();          // V[kt] complete
        __syncthreads();

        // O += P V, fully LDS.128
        #pragma unroll
        for (int kc = 0; kc < 8; kc++) {
            float4 av = *reinterpret_cast<const float4*>(Ps + (warp * 8 + kc) * 128 + lane * 4);
            uint32_t a[4] = {__float_as_uint(av.x), __float_as_uint(av.y),
                             __float_as_uint(av.z), __float_as_uint(av.w)};
            #pragma unroll
            for (int j = 0; j < 8; j++) {
                float4 bv = *reinterpret_cast<const float4*>(Vs + (j * 8 + kc) * 128 + lane * 4);
                uint32_t be[2] = {__float_as_uint(bv.x), __float_as_uint(bv.y)};
                uint32_t bo[2] = {__float_as_uint(bv.z), __float_as_uint(bv.w)};
                mma_m16n8k8(o[2*j],     a, be);
                mma_m16n8k8(o[2*j + 1], a, bo);
            }
        }
        __syncthreads();        // protect Vs + K[cur] before next iteration
    }

    // normalize + tf32-round + store O in PACKED A-operand layout
    {
        float i0 = 1.f / lrow0, i1 = 1.f / lrow1;
        const int m_tile = b * 16 + qt;
        const int m16 = warp;
        const int tl0 = (2 * t) & 3,     hi0 = (2 * t) >> 2;
        const int tl1 = (2 * t + 1) & 3, hi1 = (2 * t + 1) >> 2;
        #pragma unroll
        for (int ni = 0; ni < 16; ni++) {
            int k_tile = h * 4 + (ni >> 2);
            int k8 = ni & 3;
            size_t blk = ((((size_t)m_tile * 64 + k_tile) * 8 + m16) * 4 + k8) * 128;
            g_o[blk + (g * 4 + tl0) * 4 + hi0 * 2 + 0] = rndtf(o[ni][0] * i0);
            g_o[blk + (g * 4 + tl1) * 4 + hi1 * 2 + 0] = rndtf(o[ni][1] * i0);
            g_o[blk + (g * 4 + tl0) * 4 + hi0 * 2 + 1] = rndtf(o[ni][2] * i1);
            g_o[blk + (g * 4 + tl1) * 4 + hi1 * 2 + 1] = rndtf(o[ni][3] * i1);
        }
    }
}

// ============================================================================
extern "C" void kernel_launch(void* const* d_in, const int* in_sizes, int n_in,
                              void* d_out, int out_size) {
    const float* x  = (const float*)d_in[0];
    const float* wq = (const float*)d_in[1];
    const float* wk = (const float*)d_in[2];
    const float* wv = (const float*)d_in[3];
    const float* wo = (const float*)d_in[4];
    float* out = (float*)d_out;

    float *q, *k, *v, *o, *xr, *wr;
    cudaGetSymbolAddress((void**)&q,  g_q);
    cudaGetSymbolAddress((void**)&k,  g_k);
    cudaGetSymbolAddress((void**)&v,  g_v);
    cudaGetSymbolAddress((void**)&o,  g_o);
    cudaGetSymbolAddress((void**)&xr, g_x);
    cudaGetSymbolAddress((void**)&wr, g_w);

    cudaFuncSetAttribute(gemm_tf32_kernel, cudaFuncAttributeMaxDynamicSharedMemorySize, GEMM_SMEM);
    cudaFuncSetAttribute(attn_kernel,      cudaFuncAttributeMaxDynamicSharedMemorySize, ATTN_SMEM);

    // pack + tf32-round inputs
    const int XV = MM * HH / 4;
    const int WV = HH * HH / 4;
    pack_a_kernel<<<(XV + 255) / 256, 256>>>(x, xr, XV);
    pack_b_kernel<<<dim3((WV + 255) / 256, 4), 256>>>(wq, wk, wv, wo, wr, WV);

    dim3 gblk(256);

    // fused QKV (z selects weight + packed destination layout)
    gemm_tf32_kernel<<<dim3(HH / 128, MM / 128, 3), gblk, GEMM_SMEM>>>(
        xr, wr, q, k, v, 1);

    attn_kernel<<<dim3(SS / 128, NH, BB), 256, ATTN_SMEM>>>();

    // output projection (A = packed g_o, W = packed wo)
    gemm_tf32_kernel<<<dim3(HH / 128, MM / 128, 1), gblk, GEMM_SMEM>>>(
        o, wr + 3ull * HH * HH, out, out, out, 0);
}

// round 13
// speedup vs baseline: 1.4439x; 1.0309x over previous
#include <cuda_runtime.h>
#include <cstdint>

// Problem constants
#define BB 4
#define SS 2048
#define HH 2048
#define NH 16
#define HD 128
#define MM (BB*SS)            // 8192 rows

// Scratch (allocation-free: __device__ globals)
// ALL tensors live in fragment-packed tf32 layouts:
//   A-pack: [m16][k8][lane][4], elems [ (g,t), (8+g,t), (g,t+4), (8+g,t+4) ]
//   B-pack: [n16][k8][lane][4], elems [ (g,t), (g,t+4), (8+g,t), (8+g,t+4) ]
// g_q: per (b,h): [qt64=32][m16=4][k8=16][lane][4]    (A-operand, 8192 f/tile)
// g_k: per (b,h): [kt=32][n16=4][k8=16][lane][4]      (B-operand, 8192 f/tile)
// g_v: per (b,h): [kt=32][n16=8][k8=8][lane][4]       (B-op, n=headdim k=seq)
// g_o: packed A-operand (128-row tiles) for output GEMM; g_x packed A; g_w packed B x4.
__device__ float g_q[BB*NH*SS*HD];
__device__ float g_k[BB*NH*SS*HD];
__device__ float g_v[BB*NH*SS*HD];
__device__ float g_o[MM*HH];
__device__ float g_x[MM*HH];
__device__ float g_w[4][HH*HH];

__device__ __forceinline__ uint32_t f2tf(float f) {
    uint32_t u; asm("cvt.rna.tf32.f32 %0, %1;" : "=r"(u) : "f"(f)); return u;
}
__device__ __forceinline__ float rndtf(float f) { return __uint_as_float(f2tf(f)); }

__device__ __forceinline__ void mma_m16n8k8(float c[4], const uint32_t a[4], const uint32_t b[2]) {
    asm volatile(
        "mma.sync.aligned.m16n8k8.row.col.f32.tf32.tf32.f32 "
        "{%0,%1,%2,%3},{%4,%5,%6,%7},{%8,%9},{%0,%1,%2,%3};"
        : "+f"(c[0]), "+f"(c[1]), "+f"(c[2]), "+f"(c[3])
        : "r"(a[0]), "r"(a[1]), "r"(a[2]), "r"(a[3]), "r"(b[0]), "r"(b[1]));
}

__device__ __forceinline__ void cpa16(uint32_t s, const float* g) {
    asm volatile("cp.async.cg.shared.global [%0], [%1], 16;\n" :: "r"(s), "l"(g));
}
__device__ __forceinline__ void cpa_commit() {
    asm volatile("cp.async.commit_group;\n" ::: "memory");
}
template<int N> __device__ __forceinline__ void cpa_wait() {
    asm volatile("cp.async.wait_group %0;\n" :: "n"(N) : "memory");
}

// ============================================================================
// Input packing kernels (tf32-round + fragment layout)
// ============================================================================
__global__ void pack_a_kernel(const float* __restrict__ in, float* __restrict__ out, int ntot) {
    int o = blockIdx.x * blockDim.x + threadIdx.x;
    if (o >= ntot) return;
    int lane = o & 31, k8 = (o >> 5) & 3, m16 = (o >> 7) & 7, kt = (o >> 10) & 63;
    int mt = o >> 16;
    int g = lane >> 2, t = lane & 3;
    size_t r0 = (size_t)mt * 128 + m16 * 16 + g;
    int c0 = kt * 32 + k8 * 8 + t;
    const float* p = in + r0 * HH + c0;
    float4 v;
    v.x = rndtf(p[0]);
    v.y = rndtf(p[8 * HH]);
    v.z = rndtf(p[4]);
    v.w = rndtf(p[8 * HH + 4]);
    reinterpret_cast<float4*>(out)[o] = v;
}

__global__ void pack_b_kernel(const float* __restrict__ w0, const float* __restrict__ w1,
                              const float* __restrict__ w2, const float* __restrict__ w3,
                              float* __restrict__ out, int ntot) {
    int o = blockIdx.x * blockDim.x + threadIdx.x;
    if (o >= ntot) return;
    int z = blockIdx.y;
    const float* in = (z == 0) ? w0 : (z == 1) ? w1 : (z == 2) ? w2 : w3;
    float* dst = out + (size_t)z * HH * HH;
    int lane = o & 31, k8 = (o >> 5) & 3, n16 = (o >> 7) & 7, kt = (o >> 10) & 63;
    int nt = o >> 16;
    int g = lane >> 2, t = lane & 3;
    size_t r0 = (size_t)nt * 128 + n16 * 16 + g;
    int c0 = kt * 32 + k8 * 8 + t;
    const float* p = in + r0 * HH + c0;
    float4 v;
    v.x = rndtf(p[0]);
    v.y = rndtf(p[4]);
    v.z = rndtf(p[8 * HH]);
    v.w = rndtf(p[8 * HH + 4]);
    reinterpret_cast<float4*>(dst)[o] = v;
}

// ============================================================================
// GEMM on packed operands (tf32 mma, 128x128x32 tiles, 3-stage cp.async,
// LDS.128 fragment loads, 2 CTAs/SM).
// qkv_mode=1: epilogue writes Q (A-pack, 64-row tiles), K (B-pack),
// V (B-pack, n=d/k=s) per (b,h). qkv_mode=0: plain row-major C.
// ============================================================================
#define GSTG 3
#define STG_F 4096
#define GEMM_SMEM (GSTG * 2 * STG_F * 4) // 98304 bytes

__global__ void __launch_bounds__(256, 2) gemm_tf32_kernel(
    const float* __restrict__ Apack, const float* __restrict__ Wpack,
    float* __restrict__ Cq, float* __restrict__ Ck, float* __restrict__ Cv,
    int qkv_mode)
{
    const int N = HH;
    extern __shared__ float sm[];
    float* As = sm;
    float* Bs = sm + GSTG * STG_F;

    const int tid  = threadIdx.x;
    const int lane = tid & 31;
    const int warp = tid >> 5;
    const int g = lane >> 2, t = lane & 3;
    const int wm = warp & 3, wn = warp >> 2;
    const int mt = blockIdx.y;
    const int nt = blockIdx.x;
    const int z  = blockIdx.z;

    float* C = (z == 0) ? Cq : (z == 1) ? Ck : Cv;
    const float* Ab = Apack + ((size_t)mt * 64) * STG_F;
    const float* Bb = Wpack + (size_t)z * HH * HH + ((size_t)nt * 64) * STG_F;

    const uint32_t sA = (uint32_t)__cvta_generic_to_shared(As);
    const uint32_t sB = (uint32_t)__cvta_generic_to_shared(Bs);

    auto load_stage = [&](int s, int kt) {
        uint32_t bA = sA + (uint32_t)(s * STG_F) * 4u;
        uint32_t bB = sB + (uint32_t)(s * STG_F) * 4u;
        const float* pA = Ab + (size_t)kt * STG_F;
        const float* pB = Bb + (size_t)kt * STG_F;
        #pragma unroll
        for (int i = 0; i < 4; i++) {
            int off = i * 256 + tid;
            cpa16(bA + (uint32_t)off * 16u, pA + off * 4);
            cpa16(bB + (uint32_t)off * 16u, pB + off * 4);
        }
        cpa_commit();
    };

    float acc[2][8][4];
    #pragma unroll
    for (int mi = 0; mi < 2; mi++)
        #pragma unroll
        for (int ni = 0; ni < 8; ni++)
            #pragma unroll
            for (int j = 0; j < 4; j++) acc[mi][ni][j] = 0.f;

    load_stage(0, 0);
    load_stage(1, 1);
    cpa_wait<1>();
    __syncthreads();

    const int nk = 64;
    #pragma unroll 1
    for (int kt = 0; kt < nk; kt++) {
        const int cur = kt % GSTG;
        if (kt + 2 < nk) load_stage((kt + 2) % GSTG, kt + 2);
        else             cpa_commit();

        const float* Ac = As + cur * STG_F;
        const float* Bc = Bs + cur * STG_F;

        #pragma unroll
        for (int kk = 0; kk < 4; kk++) {
            float4 av0 = *reinterpret_cast<const float4*>(Ac + ((wm * 2 + 0) * 4 + kk) * 128 + lane * 4);
            float4 av1 = *reinterpret_cast<const float4*>(Ac + ((wm * 2 + 1) * 4 + kk) * 128 + lane * 4);
            uint32_t a0[4] = {__float_as_uint(av0.x), __float_as_uint(av0.y),
                              __float_as_uint(av0.z), __float_as_uint(av0.w)};
            uint32_t a1[4] = {__float_as_uint(av1.x), __float_as_uint(av1.y),
                              __float_as_uint(av1.z), __float_as_uint(av1.w)};
            #pragma unroll
            for (int j = 0; j < 4; j++) {
                float4 bv = *reinterpret_cast<const float4*>(Bc + ((wn * 4 + j) * 4 + kk) * 128 + lane * 4);
                uint32_t be[2] = {__float_as_uint(bv.x), __float_as_uint(bv.y)};
                uint32_t bo[2] = {__float_as_uint(bv.z), __float_as_uint(bv.w)};
                mma_m16n8k8(acc[0][2*j],     a0, be);
                mma_m16n8k8(acc[1][2*j],     a1, be);
                mma_m16n8k8(acc[0][2*j + 1], a0, bo);
                mma_m16n8k8(acc[1][2*j + 1], a1, bo);
            }
        }
        cpa_wait<1>();
        __syncthreads();
    }

    // epilogue
    const int rowBase = mt * 128;
    const int colBase = nt * 128;
    #pragma unroll
    for (int mi = 0; mi < 2; mi++) {
        int r0 = rowBase + wm * 32 + mi * 16 + g;
        #pragma unroll
        for (int ni = 0; ni < 8; ni++) {
            int cc = colBase + wn * 64 + ni * 8 + 2 * t;
            if (!qkv_mode) {
                float* dst = C + (size_t)r0 * N + cc;
                *reinterpret_cast<float2*>(dst)           = make_float2(acc[mi][ni][0], acc[mi][ni][1]);
                *reinterpret_cast<float2*>(dst + 8ull*N)  = make_float2(acc[mi][ni][2], acc[mi][ni][3]);
            } else {
                int b2 = r0 >> 11, s = r0 & 2047;
                int h2 = cc >> 7, d = cc & 127;
                int c8 = d & 7;                         // even (=2t)
                int tpa = c8 & 3, tpb = (c8 + 1) & 3, ca = c8 >> 2;
                float v0 = rndtf(acc[mi][ni][0]);
                float v1 = rndtf(acc[mi][ni][1]);
                float v2 = rndtf(acc[mi][ni][2]);
                float v3 = rndtf(acc[mi][ni][3]);
                if (z == 0) {
                    // Q: A-pack per (b,h): [qt64=32][m16=4][k8=16][128]
                    int qt2 = s >> 6, sr = s & 63;
                    float* dst = Cq + (((size_t)((b2*NH + h2)*32 + qt2)) << 13)
                               + ((sr >> 4) * 16 + (d >> 3)) * 128 + g * 16;
                    dst[tpa*4 + ca*2]     = v0;   // elem = chi*2 + rhi
                    dst[tpb*4 + ca*2]     = v1;
                    dst[tpa*4 + ca*2 + 1] = v2;
                    dst[tpb*4 + ca*2 + 1] = v3;
                } else if (z == 1) {
                    // K: B-pack per (b,h): [kt][n16=4][k8=16][128]
                    int kt2 = s >> 6, nr = s & 63;
                    float* dst = Ck + (((size_t)((b2*NH + h2)*32 + kt2)) << 13)
                               + ((nr >> 4) * 16 + (d >> 3)) * 128 + g * 16;
                    dst[tpa*4 + ca]       = v0;   // elem = nhi*2 + chi
                    dst[tpb*4 + ca]       = v1;
                    dst[tpa*4 + 2 + ca]   = v2;
                    dst[tpb*4 + 2 + ca]   = v3;
                } else {
                    // V: B-pack with n=d, k=s per (b,h): [kt][n16=8][k8=8][128]
                    int kt2 = s >> 6, sk = s & 63;
                    int k8a = sk >> 3;
                    int tpk = g & 3, chk = g >> 2;
                    int gp = d & 7, nhi = (d >> 3) & 1;
                    float* dst = Cv + (((size_t)((b2*NH + h2)*32 + kt2)) << 13)
                               + ((d >> 4) * 8 + k8a) * 128;
                    int la = (gp*4 + tpk)*4 + nhi*2 + chk;
                    int lb = la + 16;
                    dst[la]       = v0;
                    dst[lb]       = v1;
                    dst[128 + la] = v2;
                    dst[128 + lb] = v3;
                }
            }
        }
    }
}

// ============================================================================
// Flash attention (causal), tf32 mma, fragment-packed operands.
// Q tile 64 (A-pack), K tile 64 single-buffer (B-pack, prefetched after S),
// V tile 64 single-buffer (B-pack n=d, prefetched after PV), P in A-pack smem.
// 128 threads (4 warps, warp tile 16x64), 112 KB smem -> 2 CTAs/SM.
// ============================================================================
#define AQ_OFF 0          // 8192 floats
#define AK_OFF 8192       // 8192
#define AV_OFF 16384      // 8192
#define AP_OFF 24576      // 4096
#define ATTN_SMEM (28672 * 4)   // 114688 bytes -> 2 CTAs/SM

__global__ void __launch_bounds__(128, 2) attn_kernel()
{
    extern __shared__ float smf[];
    float* Qs = smf + AQ_OFF;
    float* Ks = smf + AK_OFF;
    float* Vs = smf + AV_OFF;
    float* Ps = smf + AP_OFF;

    const int tid  = threadIdx.x;
    const int lane = tid & 31;
    const int warp = tid >> 5;        // 0..3
    const int g = lane >> 2, t = lane & 3;

    const int qt = blockIdx.x;        // 0..31 (64-row Q tile)
    const int h  = blockIdx.y;
    const int b  = blockIdx.z;

    const float* Qg = g_q + (((size_t)((b*NH + h)*32 + qt)) << 13);
    const float* Kg = g_k + (((size_t)(b*NH + h)) << 18);
    const float* Vg = g_v + (((size_t)(b*NH + h)) << 18);

    const uint32_t sQ = (uint32_t)__cvta_generic_to_shared(Qs);
    const uint32_t sK = (uint32_t)__cvta_generic_to_shared(Ks);
    const uint32_t sV = (uint32_t)__cvta_generic_to_shared(Vs);

    // Q (group 1): 8192 floats = 2048 x 16B / 128 thr
    #pragma unroll
    for (int i = 0; i < 16; i++) {
        int off = i * 128 + tid;
        cpa16(sQ + (uint32_t)off * 16u, Qg + off * 4);
    }
    cpa_commit();
    // K[0] (group 2)
    #pragma unroll
    for (int i = 0; i < 16; i++) {
        int off = i * 128 + tid;
        cpa16(sK + (uint32_t)off * 16u, Kg + off * 4);
    }
    cpa_commit();
    // V[0] (group 3)
    #pragma unroll
    for (int i = 0; i < 16; i++) {
        int off = i * 128 + tid;
        cpa16(sV + (uint32_t)off * 16u, Vg + off * 4);
    }
    cpa_commit();

    float o[16][4];
    #pragma unroll
    for (int ni = 0; ni < 16; ni++)
        #pragma unroll
        for (int j = 0; j < 4; j++) o[ni][j] = 0.f;

    const float NEGINF = -1e30f;
    float mrow0 = NEGINF, mrow1 = NEGINF;
    float lrow0 = 0.f,    lrow1 = 0.f;
    const float sl = 0.088388347648318447f * 1.4426950408889634f;  // 1/sqrt(128)*log2e

    const int qrow = warp * 16 + g;
    const int nkt = qt + 1;

    #pragma unroll 1
    for (int kt = 0; kt < nkt; kt++) {
        // K[kt] ready (pending: newest is V[kt])
        cpa_wait<1>();
        __syncthreads();

        // S = Q K^T (warp tile 16x64), fully LDS.128
        float s[8][4];
        #pragma unroll
        for (int ni = 0; ni < 8; ni++)
            #pragma unroll
            for (int j = 0; j < 4; j++) s[ni][j] = 0.f;

        #pragma unroll
        for (int kk = 0; kk < 16; kk++) {
            float4 av = *reinterpret_cast<const float4*>(Qs + (warp * 16 + kk) * 128 + lane * 4);
            uint32_t a[4] = {__float_as_uint(av.x), __float_as_uint(av.y),
                             __float_as_uint(av.z), __float_as_uint(av.w)};
            #pragma unroll
            for (int nb = 0; nb < 4; nb++) {
                float4 bv = *reinterpret_cast<const float4*>(Ks + (nb * 16 + kk) * 128 + lane * 4);
                uint32_t be[2] = {__float_as_uint(bv.x), __float_as_uint(bv.y)};
                uint32_t bo[2] = {__float_as_uint(bv.z), __float_as_uint(bv.w)};
                mma_m16n8k8(s[2*nb],     a, be);
                mma_m16n8k8(s[2*nb + 1], a, bo);
            }
        }

        // Ks consumed -> prefetch K[kt+1] (overlaps softmax + PV)
        __syncthreads();
        if (kt + 1 < nkt) {
            const float* Kt = Kg + (size_t)(kt + 1) * 8192;
            #pragma unroll
            for (int i = 0; i < 16; i++) {
                int off = i * 128 + tid;
                cpa16(sK + (uint32_t)off * 16u, Kt + off * 4);
            }
        }
        cpa_commit();

        #pragma unroll
        for (int ni = 0; ni < 8; ni++)
            #pragma unroll
            for (int j = 0; j < 4; j++) s[ni][j] *= sl;

        // causal mask (only the diagonal tile crosses)
        if (kt == qt) {
            int q0 = qt * 64 + qrow;
            #pragma unroll
            for (int ni = 0; ni < 8; ni++) {
                int kg = kt * 64 + ni * 8 + 2 * t;
                if (kg     > q0)     s[ni][0] = NEGINF;
                if (kg + 1 > q0)     s[ni][1] = NEGINF;
                if (kg     > q0 + 8) s[ni][2] = NEGINF;
                if (kg + 1 > q0 + 8) s[ni][3] = NEGINF;
            }
        }

        // online softmax
        float mx0 = NEGINF, mx1 = NEGINF;
        #pragma unroll
        for (int ni = 0; ni < 8; ni++) {
            mx0 = fmaxf(mx0, fmaxf(s[ni][0], s[ni][1]));
            mx1 = fmaxf(mx1, fmaxf(s[ni][2], s[ni][3]));
        }
        mx0 = fmaxf(mx0, __shfl_xor_sync(0xffffffffu, mx0, 1));
        mx0 = fmaxf(mx0, __shfl_xor_sync(0xffffffffu, mx0, 2));
        mx1 = fmaxf(mx1, __shfl_xor_sync(0xffffffffu, mx1, 1));
        mx1 = fmaxf(mx1, __shfl_xor_sync(0xffffffffu, mx1, 2));

        float mn0 = fmaxf(mrow0, mx0), mn1 = fmaxf(mrow1, mx1);
        float al0 = exp2f(mrow0 - mn0), al1 = exp2f(mrow1 - mn1);
        mrow0 = mn0; mrow1 = mn1;

        float rs0 = 0.f, rs1 = 0.f;
        #pragma unroll
        for (int ni = 0; ni < 8; ni++) {
            s[ni][0] = exp2f(s[ni][0] - mn0); rs0 += s[ni][0];
            s[ni][1] = exp2f(s[ni][1] - mn0); rs0 += s[ni][1];
            s[ni][2] = exp2f(s[ni][2] - mn1); rs1 += s[ni][2];
            s[ni][3] = exp2f(s[ni][3] - mn1); rs1 += s[ni][3];
        }
        rs0 += __shfl_xor_sync(0xffffffffu, rs0, 1);
        rs0 += __shfl_xor_sync(0xffffffffu, rs0, 2);
        rs1 += __shfl_xor_sync(0xffffffffu, rs1, 1);
        rs1 += __shfl_xor_sync(0xffffffffu, rs1, 2);
        lrow0 = lrow0 * al0 + rs0;
        lrow1 = lrow1 * al1 + rs1;

        #pragma unroll
        for (int ni = 0; ni < 16; ni++) {
            o[ni][0] *= al0; o[ni][1] *= al0;
            o[ni][2] *= al1; o[ni][3] *= al1;
        }

        // V[kt] ready (pending: newest is K[kt+1])
        cpa_wait<1>();
        __syncthreads();

        // write P (tf32) to A-pack smem; warp-private region
        {
            const int c8 = 2 * t;
            const int tpa = c8 & 3, tpb = (c8 + 1) & 3, ca = c8 >> 2;
            #pragma unroll
            for (int ni = 0; ni < 8; ni++) {
                float* dp = Ps + (warp * 8 + ni) * 128 + g * 16;
                dp[tpa*4 + ca*2]     = rndtf(s[ni][0]);
                dp[tpb*4 + ca*2]     = rndtf(s[ni][1]);
                dp[tpa*4 + ca*2 + 1] = rndtf(s[ni][2]);
                dp[tpb*4 + ca*2 + 1] = rndtf(s[ni][3]);
            }
        }
        __syncwarp();

        // O += P V, fully LDS.128
        #pragma unroll
        for (int kc = 0; kc < 8; kc++) {
            float4 av = *reinterpret_cast<const float4*>(Ps + (warp * 8 + kc) * 128 + lane * 4);
            uint32_t a[4] = {__float_as_uint(av.x), __float_as_uint(av.y),
                             __float_as_uint(av.z), __float_as_uint(av.w)};
            #pragma unroll
            for (int j = 0; j < 8; j++) {
                float4 bv = *reinterpret_cast<const float4*>(Vs + (j * 8 + kc) * 128 + lane * 4);
                uint32_t be[2] = {__float_as_uint(bv.x), __float_as_uint(bv.y)};
                uint32_t bo[2] = {__float_as_uint(bv.z), __float_as_uint(bv.w)};
                mma_m16n8k8(o[2*j],     a, be);
                mma_m16n8k8(o[2*j + 1], a, bo);
            }
        }

        // Vs consumed -> prefetch V[kt+1] (overlaps next S-compute)
        __syncthreads();
        if (kt + 1 < nkt) {
            const float* Vt = Vg + (size_t)(kt + 1) * 8192;
            #pragma unroll
            for (int i = 0; i < 16; i++) {
                int off = i * 128 + tid;
                cpa16(sV + (uint32_t)off * 16u, Vt + off * 4);
            }
        }
        cpa_commit();
    }

    // normalize + tf32-round + store O in PACKED A-operand layout (128-row tiles)
    {
        float i0 = 1.f / lrow0, i1 = 1.f / lrow1;
        const int m_tile = b * 16 + (qt >> 1);
        const int m16 = (qt & 1) * 4 + warp;
        const int tl0 = (2 * t) & 3,     hi0 = (2 * t) >> 2;
        const int tl1 = (2 * t + 1) & 3, hi1 = (2 * t + 1) >> 2;
        #pragma unroll
        for (int ni = 0; ni < 16; ni++) {
            int k_tile = h * 4 + (ni >> 2);
            int k8 = ni & 3;
            size_t blk = ((((size_t)m_tile * 64 + k_tile) * 8 + m16) * 4 + k8) * 128;
            g_o[blk + (g * 4 + tl0) * 4 + hi0 * 2 + 0] = rndtf(o[ni][0] * i0);
            g_o[blk + (g * 4 + tl1) * 4 + hi1 * 2 + 0] = rndtf(o[ni][1] * i0);
            g_o[blk + (g * 4 + tl0) * 4 + hi0 * 2 + 1] = rndtf(o[ni][2] * i1);
            g_o[blk + (g * 4 + tl1) * 4 + hi1 * 2 + 1] = rndtf(o[ni][3] * i1);
        }
    }
}

// ============================================================================
extern "C" void kernel_launch(void* const* d_in, const int* in_sizes, int n_in,
                              void* d_out, int out_size) {
    const float* x  = (const float*)d_in[0];
    const float* wq = (const float*)d_in[1];
    const float* wk = (const float*)d_in[2];
    const float* wv = (const float*)d_in[3];
    const float* wo = (const float*)d_in[4];
    float* out = (float*)d_out;

    float *q, *k, *v, *o, *xr, *wr;
    cudaGetSymbolAddress((void**)&q,  g_q);
    cudaGetSymbolAddress((void**)&k,  g_k);
    cudaGetSymbolAddress((void**)&v,  g_v);
    cudaGetSymbolAddress((void**)&o,  g_o);
    cudaGetSymbolAddress((void**)&xr, g_x);
    cudaGetSymbolAddress((void**)&wr, g_w);

    cudaFuncSetAttribute(gemm_tf32_kernel, cudaFuncAttributeMaxDynamicSharedMemorySize, GEMM_SMEM);
    cudaFuncSetAttribute(attn_kernel,      cudaFuncAttributeMaxDynamicSharedMemorySize, ATTN_SMEM);

    // pack + tf32-round inputs
    const int XV = MM * HH / 4;
    const int WV = HH * HH / 4;
    pack_a_kernel<<<(XV + 255) / 256, 256>>>(x, xr, XV);
    pack_b_kernel<<<dim3((WV + 255) / 256, 4), 256>>>(wq, wk, wv, wo, wr, WV);

    dim3 gblk(256);

    // fused QKV (z selects weight + packed destination layout)
    gemm_tf32_kernel<<<dim3(HH / 128, MM / 128, 3), gblk, GEMM_SMEM>>>(
        xr, wr, q, k, v, 1);

    attn_kernel<<<dim3(SS / 64, NH, BB), 128, ATTN_SMEM>>>();

    // output projection (A = packed g_o, W = packed wo)
    gemm_tf32_kernel<<<dim3(HH / 128, MM / 128, 1), gblk, GEMM_SMEM>>>(
        o, wr + 3ull * HH * HH, out, out, out, 0);
}

// round 16
// speedup vs baseline: 2.8147x; 1.9494x over previous
#include <cuda_runtime.h>
#include <cuda_fp16.h>
#include <cstdint>

// Problem constants
#define BB 4
#define SS 2048
#define HH 2048
#define NH 16
#define HD 128
#define MM (BB*SS)            // 8192 rows

// Fragment-packed FP16 operand layouts (mma m16n8k16):
//  A-pack 16B/lane per m16xk16 block: u0={A[g][2t],A[g][2t+1]}, u1={A[g+8][..]},
//    u2={A[g][2t+8],[+9]}, u3={A[g+8][2t+8],[+9]}
//  B-pack 16B/lane per n16xk16 block: u0={W[g][2t],[+1]}, u1={W[g][2t+8],[+9]},
//    u2={W[g+8][2t],[+1]}, u3={W[g+8][2t+8],[+9]}
// g_x / g_o: A-pack [mt=64][ks=32][m16=8][k16=4][lane]      (1024 uint4 / slab)
// g_w[z]:    B-pack [nt=16][ks=32][n16=8][k16=4][lane]
// g_q per (b,h): [qt64=32][m16=4][k16=8][lane]              (1024 uint4 / tile)
// g_k per (b,h): [kt=32][n16=4][k16=8][lane]
// g_v per (b,h): [kt=32][n16=8][k16=4][lane]  (n=headdim, k=seq)
__device__ uint32_t g_q[BB*NH*SS*HD/2];
__device__ uint32_t g_k[BB*NH*SS*HD/2];
__device__ uint32_t g_v[BB*NH*SS*HD/2];
__device__ uint32_t g_o[MM*HH/2];
__device__ uint32_t g_x[MM*HH/2];
__device__ uint32_t g_w[4][HH*HH/2];

#define WSTRIDE_U4 (HH*HH/8)   // 524288 uint4 per packed weight

__device__ __forceinline__ uint32_t pk2(float lo, float hi) {
    uint32_t u; asm("cvt.rn.f16x2.f32 %0, %1, %2;" : "=r"(u) : "f"(hi), "f"(lo)); return u;
}

__device__ __forceinline__ void mma_fp16(float c[4], const uint32_t a[4], const uint32_t b[2]) {
    asm volatile(
        "mma.sync.aligned.m16n8k16.row.col.f32.f16.f16.f32 "
        "{%0,%1,%2,%3},{%4,%5,%6,%7},{%8,%9},{%0,%1,%2,%3};"
        : "+f"(c[0]), "+f"(c[1]), "+f"(c[2]), "+f"(c[3])
        : "r"(a[0]), "r"(a[1]), "r"(a[2]), "r"(a[3]), "r"(b[0]), "r"(b[1]));
}

__device__ __forceinline__ void cpa16(uint32_t s, const void* g) {
    asm volatile("cp.async.cg.shared.global [%0], [%1], 16;\n" :: "r"(s), "l"(g));
}
__device__ __forceinline__ void cpa_commit() {
    asm volatile("cp.async.commit_group;\n" ::: "memory");
}
template<int N> __device__ __forceinline__ void cpa_wait() {
    asm volatile("cp.async.wait_group %0;\n" :: "n"(N) : "memory");
}

// ============================================================================
// Input packing (fp32 -> fp16 fragment layout)
// index o (uint4): lane=o&31, k16=(o>>5)&3, m16=(o>>7)&7, ks=(o>>10)&31, mt=o>>15
// ============================================================================
__global__ void pack_a_kernel(const float* __restrict__ in, uint4* __restrict__ out, int ntot) {
    int o = blockIdx.x * blockDim.x + threadIdx.x;
    if (o >= ntot) return;
    int lane = o & 31, k16 = (o >> 5) & 3, m16 = (o >> 7) & 7, ks = (o >> 10) & 31;
    int mt = o >> 15;
    int g = lane >> 2, t = lane & 3;
    size_t r0 = (size_t)mt * 128 + m16 * 16 + g;
    int ca = ks * 64 + k16 * 16 + 2 * t;
    int cb = ca + 8;
    const float* p  = in + r0 * HH;
    const float* p8 = p + 8 * HH;
    uint4 v;
    v.x = pk2(p[ca],  p[ca + 1]);
    v.y = pk2(p8[ca], p8[ca + 1]);
    v.z = pk2(p[cb],  p[cb + 1]);
    v.w = pk2(p8[cb], p8[cb + 1]);
    out[o] = v;
}

__global__ void pack_b_kernel(const float* __restrict__ w0, const float* __restrict__ w1,
                              const float* __restrict__ w2, const float* __restrict__ w3,
                              uint4* __restrict__ out, int ntot) {
    int o = blockIdx.x * blockDim.x + threadIdx.x;
    if (o >= ntot) return;
    int z = blockIdx.y;
    const float* in = (z == 0) ? w0 : (z == 1) ? w1 : (z == 2) ? w2 : w3;
    uint4* dst = out + (size_t)z * WSTRIDE_U4;
    int lane = o & 31, k16 = (o >> 5) & 3, n16 = (o >> 7) & 7, ks = (o >> 10) & 31;
    int nt = o >> 15;
    int g = lane >> 2, t = lane & 3;
    size_t r0 = (size_t)nt * 128 + n16 * 16 + g;
    int ca = ks * 64 + k16 * 16 + 2 * t;
    int cb = ca + 8;
    const float* p  = in + r0 * HH;
    const float* p8 = p + 8 * HH;
    uint4 v;
    v.x = pk2(p[ca],  p[ca + 1]);
    v.y = pk2(p[cb],  p[cb + 1]);
    v.z = pk2(p8[ca], p8[ca + 1]);
    v.w = pk2(p8[cb], p8[cb + 1]);
    dst[o] = v;
}

// ============================================================================
// FP16 GEMM: C = A * W^T  (m16n8k16, CTA 128x128, BK=64/stage, 3-stage
// cp.async, 256 thr, 2 CTAs/SM).  qkv_mode=1: scatter to packed Q/K/V.
// ============================================================================
#define GSTG 3
#define STG_U4 1024                        // uint4 per A (or B) stage = 16KB
#define GEMM_SMEM (GSTG * 2 * STG_U4 * 16) // 98304 bytes

__global__ void __launch_bounds__(256, 2) gemm_fp16_kernel(
    const uint4* __restrict__ Apack, const uint4* __restrict__ Wpack,
    uint32_t* __restrict__ Cq, uint32_t* __restrict__ Ck, uint32_t* __restrict__ Cv,
    float* __restrict__ Cf, int qkv_mode)
{
    extern __shared__ uint4 sm4[];
    uint4* As = sm4;                       // [GSTG][STG_U4]
    uint4* Bs = sm4 + GSTG * STG_U4;

    const int tid  = threadIdx.x;
    const int lane = tid & 31;
    const int warp = tid >> 5;
    const int g = lane >> 2, t = lane & 3;
    const int wm = warp & 3, wn = warp >> 2;   // warp tile 32x64
    const int mt = blockIdx.y;
    const int nt = blockIdx.x;
    const int z  = blockIdx.z;

    const uint4* Ab = Apack + ((size_t)mt * 32) * STG_U4;
    const uint4* Bb = Wpack + (size_t)z * WSTRIDE_U4 + ((size_t)nt * 32) * STG_U4;

    const uint32_t sA = (uint32_t)__cvta_generic_to_shared(As);
    const uint32_t sB = (uint32_t)__cvta_generic_to_shared(Bs);

    auto load_stage = [&](int s, int ks) {
        uint32_t bA = sA + (uint32_t)(s * STG_U4) * 16u;
        uint32_t bB = sB + (uint32_t)(s * STG_U4) * 16u;
        const uint4* pA = Ab + (size_t)ks * STG_U4;
        const uint4* pB = Bb + (size_t)ks * STG_U4;
        #pragma unroll
        for (int i = 0; i < 4; i++) {
            int off = i * 256 + tid;
            cpa16(bA + (uint32_t)off * 16u, pA + off);
            cpa16(bB + (uint32_t)off * 16u, pB + off);
        }
        cpa_commit();
    };

    float acc[2][8][4];
    #pragma unroll
    for (int mi = 0; mi < 2; mi++)
        #pragma unroll
        for (int ni = 0; ni < 8; ni++)
            #pragma unroll
            for (int j = 0; j < 4; j++) acc[mi][ni][j] = 0.f;

    load_stage(0, 0);
    load_stage(1, 1);
    cpa_wait<1>();
    __syncthreads();

    const int nk = 32;      // 2048 / 64
    #pragma unroll 1
    for (int kt = 0; kt < nk; kt++) {
        const int cur = kt % GSTG;
        if (kt + 2 < nk) load_stage((kt + 2) % GSTG, kt + 2);
        else             cpa_commit();

        const uint4* Ac = As + cur * STG_U4;
        const uint4* Bc = Bs + cur * STG_U4;

        #pragma unroll
        for (int kk = 0; kk < 4; kk++) {
            uint4 av0 = Ac[((wm * 2 + 0) * 4 + kk) * 32 + lane];
            uint4 av1 = Ac[((wm * 2 + 1) * 4 + kk) * 32 + lane];
            uint32_t a0[4] = {av0.x, av0.y, av0.z, av0.w};
            uint32_t a1[4] = {av1.x, av1.y, av1.z, av1.w};
            #pragma unroll
            for (int j = 0; j < 4; j++) {
                uint4 bv = Bc[((wn * 4 + j) * 4 + kk) * 32 + lane];
                uint32_t bl[2] = {bv.x, bv.y};
                uint32_t bh[2] = {bv.z, bv.w};
                mma_fp16(acc[0][2*j],     a0, bl);
                mma_fp16(acc[1][2*j],     a1, bl);
                mma_fp16(acc[0][2*j + 1], a0, bh);
                mma_fp16(acc[1][2*j + 1], a1, bh);
            }
        }
        cpa_wait<1>();
        __syncthreads();
    }

    // epilogue
    const int rowBase = mt * 128;
    const int colBase = nt * 128;
    #pragma unroll
    for (int mi = 0; mi < 2; mi++) {
        int r0 = rowBase + wm * 32 + mi * 16 + g;
        #pragma unroll
        for (int ni = 0; ni < 8; ni++) {
            int cc = colBase + wn * 64 + ni * 8 + 2 * t;
            if (!qkv_mode) {
                float* dst = Cf + (size_t)r0 * HH + cc;
                *reinterpret_cast<float2*>(dst)            = make_float2(acc[mi][ni][0], acc[mi][ni][1]);
                *reinterpret_cast<float2*>(dst + 8ull*HH)  = make_float2(acc[mi][ni][2], acc[mi][ni][3]);
            } else {
                int b2 = r0 >> 11, s = r0 & 2047;
                int h2 = cc >> 7, d = cc & 127;
                int c2 = d & 15;
                if (z == 0) {
                    int uix = (c2 & 8) ? 2 : 0;
                    int lanep = g * 4 + ((c2 & 7) >> 1);
                    size_t idx = ((size_t)((b2*NH + h2)*32 + (s >> 6))) * 4096
                               + (((s & 63) >> 4) * 8 + (d >> 4)) * 128 + lanep * 4;
                    Cq[idx + uix]     = pk2(acc[mi][ni][0], acc[mi][ni][1]);
                    Cq[idx + uix + 1] = pk2(acc[mi][ni][2], acc[mi][ni][3]);
                } else if (z == 1) {
                    int uix = (c2 & 8) ? 1 : 0;
                    int lanep = g * 4 + ((c2 & 7) >> 1);
                    size_t idx = ((size_t)((b2*NH + h2)*32 + (s >> 6))) * 4096
                               + (((s & 63) >> 4) * 8 + (d >> 4)) * 128 + lanep * 4;
                    Ck[idx + uix]     = pk2(acc[mi][ni][0], acc[mi][ni][1]);
                    Ck[idx + uix + 2] = pk2(acc[mi][ni][2], acc[mi][ni][3]);
                } else {
                    // V: n = d, k = s
                    __half* Vh = (__half*)Cv;
                    int n2 = d & 15, gn = n2 & 7, nu = n2 >> 3;
                    int tk = g >> 1, hf = g & 1;
                    size_t base = ((size_t)((b2*NH + h2)*32 + (s >> 6))) * 4096
                                + ((d >> 4) * 4 + ((s & 63) >> 4)) * 128;
                    size_t a0i = (base + (gn*4 + tk)     * 4 + nu*2) * 2 + hf;
                    size_t a1i = (base + (gn*4 + tk + 4) * 4 + nu*2) * 2 + hf;
                    Vh[a0i]     = __float2half_rn(acc[mi][ni][0]);
                    Vh[a1i]     = __float2half_rn(acc[mi][ni][1]);
                    Vh[a0i + 2] = __float2half_rn(acc[mi][ni][2]);
                    Vh[a1i + 2] = __float2half_rn(acc[mi][ni][3]);
                }
            }
        }
    }
}

// ============================================================================
// Flash attention (causal), fp16 mma m16n8k16, fragment-packed operands.
// Q tile 64, K/V tile 64 single-buffer with post-consume prefetch, P in
// A-pack smem. 128 threads (4 warps x 16 q-rows), 56KB smem -> 3 CTAs/SM.
// ============================================================================
#define AQ_U4 0
#define AK_U4 1024
#define AV_U4 2048
#define AP_U4 3072
#define ATTN_SMEM (3584 * 16)   // 57344 bytes

__global__ void __launch_bounds__(128, 3) attn_kernel()
{
    extern __shared__ uint4 smq[];
    uint4* Qs = smq + AQ_U4;
    uint4* Ks = smq + AK_U4;
    uint4* Vs = smq + AV_U4;
    uint4* Ps = smq + AP_U4;

    const int tid  = threadIdx.x;
    const int lane = tid & 31;
    const int warp = tid >> 5;        // 0..3
    const int g = lane >> 2, t = lane & 3;

    const int qt = blockIdx.x;        // 0..31
    const int h  = blockIdx.y;
    const int b  = blockIdx.z;

    const int bh = b * NH + h;
    const uint4* Qg = reinterpret_cast<const uint4*>(g_q) + ((size_t)(bh * 32 + qt)) * 1024;
    const uint4* Kg = reinterpret_cast<const uint4*>(g_k) + ((size_t)bh * 32) * 1024;
    const uint4* Vg = reinterpret_cast<const uint4*>(g_v) + ((size_t)bh * 32) * 1024;

    const uint32_t sQ = (uint32_t)__cvta_generic_to_shared(Qs);
    const uint32_t sK = (uint32_t)__cvta_generic_to_shared(Ks);
    const uint32_t sV = (uint32_t)__cvta_generic_to_shared(Vs);

    // Q (group 1), K[0] (group 2), V[0] (group 3)
    #pragma unroll
    for (int i = 0; i < 8; i++) {
        int off = i * 128 + tid;
        cpa16(sQ + (uint32_t)off * 16u, Qg + off);
    }
    cpa_commit();
    #pragma unroll
    for (int i = 0; i < 8; i++) {
        int off = i * 128 + tid;
        cpa16(sK + (uint32_t)off * 16u, Kg + off);
    }
    cpa_commit();
    #pragma unroll
    for (int i = 0; i < 8; i++) {
        int off = i * 128 + tid;
        cpa16(sV + (uint32_t)off * 16u, Vg + off);
    }
    cpa_commit();

    float o[16][4];
    #pragma unroll
    for (int ni = 0; ni < 16; ni++)
        #pragma unroll
        for (int j = 0; j < 4; j++) o[ni][j] = 0.f;

    const float NEGINF = -1e30f;
    float mrow0 = NEGINF, mrow1 = NEGINF;
    float lrow0 = 0.f,    lrow1 = 0.f;
    const float sl = 0.088388347648318447f * 1.4426950408889634f;  // 1/sqrt(128)*log2e

    const int qrow = warp * 16 + g;
    const int nkt = qt + 1;

    #pragma unroll 1
    for (int kt = 0; kt < nkt; kt++) {
        // K[kt] ready (newest pending = V[kt])
        cpa_wait<1>();
        __syncthreads();

        // S = Q K^T : 8 k16-steps
        float s[8][4];
        #pragma unroll
        for (int ni = 0; ni < 8; ni++)
            #pragma unroll
            for (int j = 0; j < 4; j++) s[ni][j] = 0.f;

        #pragma unroll
        for (int kk = 0; kk < 8; kk++) {
            uint4 av = Qs[(warp * 8 + kk) * 32 + lane];
            uint32_t a[4] = {av.x, av.y, av.z, av.w};
            #pragma unroll
            for (int nb = 0; nb < 4; nb++) {
                uint4 bv = Ks[(nb * 8 + kk) * 32 + lane];
                uint32_t bl[2] = {bv.x, bv.y};
                uint32_t bh2[2] = {bv.z, bv.w};
                mma_fp16(s[2*nb],     a, bl);
                mma_fp16(s[2*nb + 1], a, bh2);
            }
        }

        // Ks consumed -> prefetch K[kt+1]
        __syncthreads();
        if (kt + 1 < nkt) {
            const uint4* Kt = Kg + (size_t)(kt + 1) * 1024;
            #pragma unroll
            for (int i = 0; i < 8; i++) {
                int off = i * 128 + tid;
                cpa16(sK + (uint32_t)off * 16u, Kt + off);
            }
        }
        cpa_commit();

        #pragma unroll
        for (int ni = 0; ni < 8; ni++)
            #pragma unroll
            for (int j = 0; j < 4; j++) s[ni][j] *= sl;

        // causal mask (diagonal tile only)
        if (kt == qt) {
            int q0 = qt * 64 + qrow;
            #pragma unroll
            for (int ni = 0; ni < 8; ni++) {
                int kg = kt * 64 + ni * 8 + 2 * t;
                if (kg     > q0)     s[ni][0] = NEGINF;
                if (kg + 1 > q0)     s[ni][1] = NEGINF;
                if (kg     > q0 + 8) s[ni][2] = NEGINF;
                if (kg + 1 > q0 + 8) s[ni][3] = NEGINF;
            }
        }

        // online softmax
        float mx0 = NEGINF, mx1 = NEGINF;
        #pragma unroll
        for (int ni = 0; ni < 8; ni++) {
            mx0 = fmaxf(mx0, fmaxf(s[ni][0], s[ni][1]));
            mx1 = fmaxf(mx1, fmaxf(s[ni][2], s[ni][3]));
        }
        mx0 = fmaxf(mx0, __shfl_xor_sync(0xffffffffu, mx0, 1));
        mx0 = fmaxf(mx0, __shfl_xor_sync(0xffffffffu, mx0, 2));
        mx1 = fmaxf(mx1, __shfl_xor_sync(0xffffffffu, mx1, 1));
        mx1 = fmaxf(mx1, __shfl_xor_sync(0xffffffffu, mx1, 2));

        float mn0 = fmaxf(mrow0, mx0), mn1 = fmaxf(mrow1, mx1);
        float al0 = exp2f(mrow0 - mn0), al1 = exp2f(mrow1 - mn1);
        mrow0 = mn0; mrow1 = mn1;

        float rs0 = 0.f, rs1 = 0.f;
        #pragma unroll
        for (int ni = 0; ni < 8; ni++) {
            s[ni][0] = exp2f(s[ni][0] - mn0); rs0 += s[ni][0];
            s[ni][1] = exp2f(s[ni][1] - mn0); rs0 += s[ni][1];
            s[ni][2] = exp2f(s[ni][2] - mn1); rs1 += s[ni][2];
            s[ni][3] = exp2f(s[ni][3] - mn1); rs1 += s[ni][3];
        }
        rs0 += __shfl_xor_sync(0xffffffffu, rs0, 1);
        rs0 += __shfl_xor_sync(0xffffffffu, rs0, 2);
        rs1 += __shfl_xor_sync(0xffffffffu, rs1, 1);
        rs1 += __shfl_xor_sync(0xffffffffu, rs1, 2);
        lrow0 = lrow0 * al0 + rs0;
        lrow1 = lrow1 * al1 + rs1;

        #pragma unroll
        for (int ni = 0; ni < 16; ni++) {
            o[ni][0] *= al0; o[ni][1] *= al0;
            o[ni][2] *= al1; o[ni][3] *= al1;
        }

        // V[kt] ready (newest pending = K[kt+1])
        cpa_wait<1>();
        __syncthreads();

        // write P (fp16) into A-pack smem; warp-private
        {
            uint32_t* Pu = reinterpret_cast<uint32_t*>(Ps);
            #pragma unroll
            for (int ni = 0; ni < 8; ni++) {
                int c  = ni * 8 + 2 * t;
                int k16 = c >> 4, c2 = c & 15;
                int uix = (c2 & 8) ? 2 : 0;
                int lanep = g * 4 + ((c2 & 7) >> 1);
                uint32_t idx = ((warp * 4 + k16) * 32 + lanep) * 4;
                Pu[idx + uix]     = pk2(s[ni][0], s[ni][1]);
                Pu[idx + uix + 1] = pk2(s[ni][2], s[ni][3]);
            }
        }
        __syncwarp();

        // O += P V : 4 k16-steps
        #pragma unroll
        for (int kc = 0; kc < 4; kc++) {
            uint4 av = Ps[(warp * 4 + kc) * 32 + lane];
            uint32_t a[4] = {av.x, av.y, av.z, av.w};
            #pragma unroll
            for (int j = 0; j < 8; j++) {
                uint4 bv = Vs[(j * 4 + kc) * 32 + lane];
                uint32_t bl[2] = {bv.x, bv.y};
                uint32_t bh2[2] = {bv.z, bv.w};
                mma_fp16(o[2*j],     a, bl);
                mma_fp16(o[2*j + 1], a, bh2);
            }
        }

        // Vs consumed -> prefetch V[kt+1]
        __syncthreads();
        if (kt + 1 < nkt) {
            const uint4* Vt = Vg + (size_t)(kt + 1) * 1024;
            #pragma unroll
            for (int i = 0; i < 8; i++) {
                int off = i * 128 + tid;
                cpa16(sV + (uint32_t)off * 16u, Vt + off);
            }
        }
        cpa_commit();
    }

    // normalize + store O into packed A layout (fp16) for the output GEMM
    {
        float i0 = 1.f / lrow0, i1 = 1.f / lrow1;
        const int m_tile = b * 16 + (qt >> 1);
        const int m16o = (qt & 1) * 4 + warp;
        #pragma unroll
        for (int ni = 0; ni < 16; ni++) {
            int dl = ni * 8 + 2 * t;
            int Kg2 = h * 128 + dl;
            int ks = Kg2 >> 6, k16 = (Kg2 >> 4) & 3, c2 = dl & 15;
            int uix = (c2 & 8) ? 2 : 0;
            int lanep = g * 4 + ((c2 & 7) >> 1);
            size_t idx = ((((size_t)m_tile * 32 + ks) * 8 + m16o) * 4 + k16) * 128 + lanep * 4;
            g_o[idx + uix]     = pk2(o[ni][0] * i0, o[ni][1] * i0);
            g_o[idx + uix + 1] = pk2(o[ni][2] * i1, o[ni][3] * i1);
        }
    }
}

// ============================================================================
extern "C" void kernel_launch(void* const* d_in, const int* in_sizes, int n_in,
                              void* d_out, int out_size) {
    const float* x  = (const float*)d_in[0];
    const float* wq = (const float*)d_in[1];
    const float* wk = (const float*)d_in[2];
    const float* wv = (const float*)d_in[3];
    const float* wo = (const float*)d_in[4];
    float* out = (float*)d_out;

    uint32_t *q, *k, *v, *o, *xr, *wr;
    cudaGetSymbolAddress((void**)&q,  g_q);
    cudaGetSymbolAddress((void**)&k,  g_k);
    cudaGetSymbolAddress((void**)&v,  g_v);
    cudaGetSymbolAddress((void**)&o,  g_o);
    cudaGetSymbolAddress((void**)&xr, g_x);
    cudaGetSymbolAddress((void**)&wr, g_w);

    cudaFuncSetAttribute(gemm_fp16_kernel, cudaFuncAttributeMaxDynamicSharedMemorySize, GEMM_SMEM);
    cudaFuncSetAttribute(attn_kernel,      cudaFuncAttributeMaxDynamicSharedMemorySize, ATTN_SMEM);

    // pack fp32 -> fp16 fragment layouts
    const int XV = MM * HH / 8;   // uint4 vectors
    const int WV = HH * HH / 8;
    pack_a_kernel<<<(XV + 255) / 256, 256>>>(x, (uint4*)xr, XV);
    pack_b_kernel<<<dim3((WV + 255) / 256, 4), 256>>>(wq, wk, wv, wo, (uint4*)wr, WV);

    dim3 gblk(256);

    // fused QKV (z selects weight + packed destination)
    gemm_fp16_kernel<<<dim3(HH / 128, MM / 128, 3), gblk, GEMM_SMEM>>>(
        (const uint4*)xr, (const uint4*)wr, q, k, v, nullptr, 1);

    attn_kernel<<<dim3(SS / 64, NH, BB), 128, ATTN_SMEM>>>();

    // output projection (A = packed g_o, W = packed wo)
    gemm_fp16_kernel<<<dim3(HH / 128, MM / 128, 1), gblk, GEMM_SMEM>>>(
        (const uint4*)o, (const uint4*)wr + 3ull * WSTRIDE_U4,
        nullptr, nullptr, nullptr, out, 0);
}